// round 8
// baseline (speedup 1.0000x reference)
#include <cuda_runtime.h>
#include <cuda_fp16.h>
#include <mma.h>
#include <math.h>
#include <stdint.h>

using namespace nvcuda;

#define NN 100000
#define EE 1600000
#define DD 256
#define DE 8
#define HF 128
#define NEG_SLOPE 0.2f
#define NB ((NN + 1023) / 1024)   // scan blocks = 98

// ---------------- scratch (device globals) ----------------------------------
__device__ __half  g_feat_h[(size_t)NN * DD];
__device__ __half  g_wsrc_h[HF * DD];
__device__ __half  g_wdst_h[HF * DD];
__device__ __half  g_wngnn_h[HF * HF];
__device__ __half  g_hsrc_h[(size_t)NN * HF];
__device__ float   g_hdst[(size_t)NN * HF];
__device__ __half  g_rst_h[(size_t)NN * HF];
__device__ float2  g_asrc[NN];
__device__ float2  g_adst[NN];
__device__ float2  g_ep  [EE];
__device__ int     g_cnt [NN];
__device__ int     g_off [NN + 1];
__device__ int     g_cur [NN];
__device__ int     g_psrc[EE];
__device__ int     g_tmp [NN];
__device__ int     g_bsum[128];

// ---------------- cp.async helpers -------------------------------------------
static __device__ __forceinline__ void cp16(__half* s, const __half* g, bool pred) {
    unsigned sa = (unsigned)__cvta_generic_to_shared(s);
    int sz = pred ? 16 : 0;
    asm volatile("cp.async.ca.shared.global [%0], [%1], 16, %2;"
                 :: "r"(sa), "l"(g), "r"(sz));
}
static __device__ __forceinline__ void cp_commit() {
    asm volatile("cp.async.commit_group;" ::: "memory");
}
template <int N>
static __device__ __forceinline__ void cp_wait() {
    asm volatile("cp.async.wait_group %0;" :: "n"(N) : "memory");
}

// ---------------- fused: feat fp32->fp16 + attention logits ------------------
static __device__ __forceinline__ float dot8(float4 x0, float4 x1,
                                             float4 w0, float4 w1) {
    float s = x0.x * w0.x;
    s = fmaf(x0.y, w0.y, s); s = fmaf(x0.z, w0.z, s); s = fmaf(x0.w, w0.w, s);
    s = fmaf(x1.x, w1.x, s); s = fmaf(x1.y, w1.y, s);
    s = fmaf(x1.z, w1.z, s); s = fmaf(x1.w, w1.w, s);
    return s;
}

__global__ void feat_attn_kernel(const float* __restrict__ feat,
                                 const float* __restrict__ Was,
                                 const float* __restrict__ Wad) {
    int lane = threadIdx.x & 31;
    int warp = (blockIdx.x * blockDim.x + threadIdx.x) >> 5;
    int nwarps = (gridDim.x * blockDim.x) >> 5;
    int cb = lane * 8;

    float4 ws0a = *(const float4*)(Was + cb);
    float4 ws0b = *(const float4*)(Was + cb + 4);
    float4 ws1a = *(const float4*)(Was + DD + cb);
    float4 ws1b = *(const float4*)(Was + DD + cb + 4);
    float4 wd0a = *(const float4*)(Wad + cb);
    float4 wd0b = *(const float4*)(Wad + cb + 4);
    float4 wd1a = *(const float4*)(Wad + DD + cb);
    float4 wd1b = *(const float4*)(Wad + DD + cb + 4);

    for (int n = warp; n < NN; n += nwarps) {
        const float* fp = feat + (size_t)n * DD + cb;
        float4 x0 = *(const float4*)fp;
        float4 x1 = *(const float4*)(fp + 4);

        __half2 h[4] = {__floats2half2_rn(x0.x, x0.y),
                        __floats2half2_rn(x0.z, x0.w),
                        __floats2half2_rn(x1.x, x1.y),
                        __floats2half2_rn(x1.z, x1.w)};
        *(uint4*)(g_feat_h + (size_t)n * DD + cb) = *(uint4*)h;

        float s0 = dot8(x0, x1, ws0a, ws0b);
        float s1 = dot8(x0, x1, ws1a, ws1b);
        float d0 = dot8(x0, x1, wd0a, wd0b);
        float d1 = dot8(x0, x1, wd1a, wd1b);
#pragma unroll
        for (int off = 16; off > 0; off >>= 1) {
            s0 += __shfl_xor_sync(0xffffffff, s0, off);
            s1 += __shfl_xor_sync(0xffffffff, s1, off);
            d0 += __shfl_xor_sync(0xffffffff, d0, off);
            d1 += __shfl_xor_sync(0xffffffff, d1, off);
        }
        if (lane == 0) {
            g_asrc[n] = make_float2(s0, s1);
            g_adst[n] = make_float2(d0, d1);
        }
    }
}

// ---------------- weight conversions (one launch) ----------------------------
__global__ void wconv_kernel(const float* __restrict__ Wsrc,
                             const float* __restrict__ Wdst,
                             const float* __restrict__ Wngnn) {
    int i = blockIdx.x * blockDim.x + threadIdx.x;
    const int n1 = HF * DD / 8, n2 = 2 * n1, n3 = n2 + HF * HF / 8;
    const float* src;
    __half* dst;
    int k;
    if (i < n1)      { src = Wsrc;  dst = g_wsrc_h;  k = i; }
    else if (i < n2) { src = Wdst;  dst = g_wdst_h;  k = i - n1; }
    else if (i < n3) { src = Wngnn; dst = g_wngnn_h; k = i - n2; }
    else return;
    const float4* s = (const float4*)(src + (size_t)k * 8);
    float4 a = s[0], b = s[1];
    __half2 h[4] = {__floats2half2_rn(a.x, a.y), __floats2half2_rn(a.z, a.w),
                    __floats2half2_rn(b.x, b.y), __floats2half2_rn(b.z, b.w)};
    *(uint4*)(dst + (size_t)k * 8) = *(uint4*)h;
}

// ---------------- CSR build --------------------------------------------------
__global__ void hist_kernel(const int* __restrict__ ed) {
    int i = blockIdx.x * blockDim.x + threadIdx.x;
    if (i < EE) atomicAdd(&g_cnt[ed[i]], 1);
}

__global__ void scan1_kernel() {
    __shared__ int sh[1024];
    int t = threadIdx.x;
    int gi = blockIdx.x * 1024 + t;
    int v = (gi < NN) ? g_cnt[gi] : 0;
    sh[t] = v;
    __syncthreads();
#pragma unroll
    for (int off = 1; off < 1024; off <<= 1) {
        int add = (t >= off) ? sh[t - off] : 0;
        __syncthreads();
        sh[t] += add;
        __syncthreads();
    }
    if (gi < NN) g_tmp[gi] = sh[t] - v;
    if (t == 1023) g_bsum[blockIdx.x] = sh[1023];
}

__global__ void scan2_kernel() {
    __shared__ int sh[128];
    int t = threadIdx.x;
    int v = (t < NB) ? g_bsum[t] : 0;
    sh[t] = v;
    __syncthreads();
#pragma unroll
    for (int off = 1; off < 128; off <<= 1) {
        int add = (t >= off) ? sh[t - off] : 0;
        __syncthreads();
        sh[t] += add;
        __syncthreads();
    }
    if (t < NB) g_bsum[t] = sh[t] - v;
}

__global__ void scan3_kernel() {
    int i = blockIdx.x * blockDim.x + threadIdx.x;
    if (i < NN) {
        int o = g_tmp[i] + g_bsum[i >> 10];
        g_off[i] = o;
        g_cur[i] = o;
    }
    if (i == 0) g_off[NN] = EE;
}

// ---------------- fused: CSR scatter + edge logit + leaky + exp --------------
__global__ void scatter_edge_kernel(const int* __restrict__ es,
                                    const int* __restrict__ ed,
                                    const float* __restrict__ fe,
                                    const float* __restrict__ Wae) {
    int i = blockIdx.x * blockDim.x + threadIdx.x;
    if (i >= EE) return;

    int s = es[i], d = ed[i];
    int pos = atomicAdd(&g_cur[d], 1);
    g_psrc[pos] = s;

    float4 x0 = *(const float4*)(fe + (size_t)i * DE);
    float4 x1 = *(const float4*)(fe + (size_t)i * DE + 4);

    float ae0 = x0.x * __ldg(Wae + 0) + x0.y * __ldg(Wae + 1) +
                x0.z * __ldg(Wae + 2) + x0.w * __ldg(Wae + 3) +
                x1.x * __ldg(Wae + 4) + x1.y * __ldg(Wae + 5) +
                x1.z * __ldg(Wae + 6) + x1.w * __ldg(Wae + 7);
    float ae1 = x0.x * __ldg(Wae + 8)  + x0.y * __ldg(Wae + 9) +
                x0.z * __ldg(Wae + 10) + x0.w * __ldg(Wae + 11) +
                x1.x * __ldg(Wae + 12) + x1.y * __ldg(Wae + 13) +
                x1.z * __ldg(Wae + 14) + x1.w * __ldg(Wae + 15);

    float2 as = g_asrc[s];
    float2 ad = g_adst[d];
    float e0 = as.x + ad.x + ae0;
    float e1 = as.y + ad.y + ae1;
    e0 = (e0 >= 0.f) ? e0 : NEG_SLOPE * e0;
    e1 = (e1 >= 0.f) ? e1 : NEG_SLOPE * e1;
    g_ep[pos] = make_float2(__expf(e0), __expf(e1));
}

// ---------------- tensor-core GEMM with cp.async double buffering ------------
// C[*,128] = A[M,K] @ B[128,K]^T ; 128x128x32 CTA tile, 8 warps
#define LDA 40
#define LDC 132
#define TILE_BYTES (128 * LDA * 2)     // 10240 B per half-tile buffer
__global__ void __launch_bounds__(256)
gemm_h_kernel(const __half* __restrict__ A,
              const __half* __restrict__ B0, const __half* __restrict__ B1,
              const float* __restrict__ bias0, const float* __restrict__ bias1,
              const float* __restrict__ add,
              float* __restrict__ C0f, float* __restrict__ C1f,
              __half* __restrict__ C0h,
              int M, int K, int mode) {
    extern __shared__ char dynsm[];
    __half* Asb[2] = {(__half*)dynsm, (__half*)(dynsm + TILE_BYTES)};
    __half* Bsb[2] = {(__half*)(dynsm + 2 * TILE_BYTES),
                      (__half*)(dynsm + 3 * TILE_BYTES)};
    float*  Cs = (float*)dynsm;        // reused after mainloop

    const __half* B    = (blockIdx.x == 0) ? B0 : B1;
    const float*  bias = (blockIdx.x == 0) ? bias0 : bias1;
    bool h_out = (blockIdx.x == 0) && (C0h != nullptr);

    int bm = blockIdx.y * 128;
    int t  = threadIdx.x;
    int w  = t >> 5;
    int wm = w & 3;
    int wn = w >> 2;

    int lr = t >> 1;              // load row 0..127
    int lh = (t & 1) * 16;        // 16-half chunk

    int arow = bm + lr;
    bool ap_ok = (arow < M);
    int arow_c = ap_ok ? arow : (M - 1);   // clamp (src-size 0 when !ap_ok)
    const __half* a_base = A + (size_t)arow_c * K + lh;
    const __half* b_base = B + (size_t)lr * K + lh;

    wmma::fragment<wmma::accumulator, 16, 16, 16, float> cf[2][4];
#pragma unroll
    for (int i = 0; i < 2; i++)
#pragma unroll
        for (int j = 0; j < 4; j++) wmma::fill_fragment(cf[i][j], 0.0f);

    const int nIter = K >> 5;

    // prologue: prefetch tile 0
    cp16(&Asb[0][lr * LDA + lh], a_base, ap_ok);
    cp16(&Asb[0][lr * LDA + lh + 8], a_base + 8, ap_ok);
    cp16(&Bsb[0][lr * LDA + lh], b_base, true);
    cp16(&Bsb[0][lr * LDA + lh + 8], b_base + 8, true);
    cp_commit();

    for (int it = 0; it < nIter; it++) {
        int buf = it & 1;
        if (it + 1 < nIter) {
            int kt = (it + 1) << 5;
            cp16(&Asb[buf ^ 1][lr * LDA + lh], a_base + kt, ap_ok);
            cp16(&Asb[buf ^ 1][lr * LDA + lh + 8], a_base + kt + 8, ap_ok);
            cp16(&Bsb[buf ^ 1][lr * LDA + lh], b_base + kt, true);
            cp16(&Bsb[buf ^ 1][lr * LDA + lh + 8], b_base + kt + 8, true);
            cp_commit();
            cp_wait<1>();
        } else {
            cp_wait<0>();
        }
        __syncthreads();

        __half* As = Asb[buf];
        __half* Bs = Bsb[buf];
#pragma unroll
        for (int ks = 0; ks < 32; ks += 16) {
            wmma::fragment<wmma::matrix_a, 16, 16, 16, __half, wmma::row_major> af[2];
            wmma::fragment<wmma::matrix_b, 16, 16, 16, __half, wmma::col_major> bf[4];
#pragma unroll
            for (int i = 0; i < 2; i++)
                wmma::load_matrix_sync(af[i], &As[(wm * 32 + i * 16) * LDA + ks], LDA);
#pragma unroll
            for (int j = 0; j < 4; j++)
                wmma::load_matrix_sync(bf[j], &Bs[(wn * 64 + j * 16) * LDA + ks], LDA);
#pragma unroll
            for (int i = 0; i < 2; i++)
#pragma unroll
                for (int j = 0; j < 4; j++)
                    wmma::mma_sync(cf[i][j], af[i], bf[j], cf[i][j]);
        }
        __syncthreads();
    }

    // stage C through smem (reuses buffers)
#pragma unroll
    for (int i = 0; i < 2; i++)
#pragma unroll
        for (int j = 0; j < 4; j++)
            wmma::store_matrix_sync(&Cs[(wm * 32 + i * 16) * LDC + wn * 64 + j * 16],
                                    cf[i][j], LDC, wmma::mem_row_major);
    __syncthreads();

    {
        int r = t >> 1;
        int cb = (t & 1) * 64;
        int row = bm + r;
        if (row < M) {
#pragma unroll
            for (int j = 0; j < 64; j += 4) {
                float4 v = *(float4*)&Cs[r * LDC + cb + j];
                if (bias) {
                    float4 b = *(const float4*)(bias + cb + j);
                    v.x += b.x; v.y += b.y; v.z += b.z; v.w += b.w;
                }
                if (mode == 1) {
                    float4 rs = *(const float4*)(add + (size_t)row * HF + cb + j);
                    v.x = fmaxf(v.x, 0.f) + rs.x;
                    v.y = fmaxf(v.y, 0.f) + rs.y;
                    v.z = fmaxf(v.z, 0.f) + rs.z;
                    v.w = fmaxf(v.w, 0.f) + rs.w;
                }
                if (h_out) {
                    __half2 p[2] = {__floats2half2_rn(v.x, v.y),
                                    __floats2half2_rn(v.z, v.w)};
                    *(uint2*)(C0h + (size_t)row * HF + cb + j) = *(uint2*)p;
                } else {
                    float* Cf = (blockIdx.x == 0) ? C0f : C1f;
                    *(float4*)(Cf + (size_t)row * HF + cb + j) = v;
                }
            }
        }
    }
}

// ---------------- pull aggregation: warp per dst node ------------------------
__global__ void agg_kernel() {
    int warp = (blockIdx.x * blockDim.x + threadIdx.x) >> 5;
    if (warp >= NN) return;
    int lane = threadIdx.x & 31;

    int row = g_off[warp];
    int end = g_off[warp + 1];

    float z0 = 0.f, z1 = 0.f;
    for (int j = row + lane; j < end; j += 32) {
        float2 e = g_ep[j];
        z0 += e.x;
        z1 += e.y;
    }
#pragma unroll
    for (int off = 16; off > 0; off >>= 1) {
        z0 += __shfl_xor_sync(0xffffffff, z0, off);
        z1 += __shfl_xor_sync(0xffffffff, z1, off);
    }
    float invz = __fdividef(1.f, (lane < 16) ? z0 : z1);

    const int elem = lane * 4;
    float a0 = 0.f, a1 = 0.f, a2 = 0.f, a3 = 0.f;

    int j = row;
    for (; j + 2 <= end; j += 2) {
        float2 e0 = g_ep[j];
        float2 e1 = g_ep[j + 1];
        int s0 = g_psrc[j];
        int s1 = g_psrc[j + 1];
        float c0 = ((lane < 16) ? e0.x : e0.y) * invz;
        float c1 = ((lane < 16) ? e1.x : e1.y) * invz;
        const __half2* p0 = (const __half2*)(g_hsrc_h + (size_t)s0 * HF + elem);
        const __half2* p1 = (const __half2*)(g_hsrc_h + (size_t)s1 * HF + elem);
        __half2 u0 = p0[0], u1 = p0[1];
        __half2 v0 = p1[0], v1 = p1[1];
        float2 fu0 = __half22float2(u0), fu1 = __half22float2(u1);
        float2 fv0 = __half22float2(v0), fv1 = __half22float2(v1);
        a0 = fmaf(fu0.x, c0, a0); a1 = fmaf(fu0.y, c0, a1);
        a2 = fmaf(fu1.x, c0, a2); a3 = fmaf(fu1.y, c0, a3);
        a0 = fmaf(fv0.x, c1, a0); a1 = fmaf(fv0.y, c1, a1);
        a2 = fmaf(fv1.x, c1, a2); a3 = fmaf(fv1.y, c1, a3);
    }
    if (j < end) {
        float2 e0 = g_ep[j];
        int s0 = g_psrc[j];
        float c0 = ((lane < 16) ? e0.x : e0.y) * invz;
        const __half2* p0 = (const __half2*)(g_hsrc_h + (size_t)s0 * HF + elem);
        __half2 u0 = p0[0], u1 = p0[1];
        float2 fu0 = __half22float2(u0), fu1 = __half22float2(u1);
        a0 = fmaf(fu0.x, c0, a0); a1 = fmaf(fu0.y, c0, a1);
        a2 = fmaf(fu1.x, c0, a2); a3 = fmaf(fu1.y, c0, a3);
    }
    __half2 hh[2] = {__floats2half2_rn(a0, a1), __floats2half2_rn(a2, a3)};
    *(uint2*)(g_rst_h + (size_t)warp * HF + elem) = *(uint2*)hh;
}

// ---------------- launch -----------------------------------------------------
extern "C" void kernel_launch(void* const* d_in, const int* in_sizes, int n_in,
                              void* d_out, int out_size) {
    const float* feat_src    = (const float*)d_in[0];
    const float* feat_edge   = (const float*)d_in[1];
    const int*   edge_src    = (const int*)d_in[2];
    const int*   edge_dst    = (const int*)d_in[3];
    const float* W_src       = (const float*)d_in[4];
    const float* W_dst       = (const float*)d_in[5];
    const float* b_dst       = (const float*)d_in[6];
    const float* W_attn_src  = (const float*)d_in[7];
    const float* W_attn_dst  = (const float*)d_in[8];
    const float* W_attn_edge = (const float*)d_in[9];
    const float* W_ngnn      = (const float*)d_in[10];
    const float* b_ngnn      = (const float*)d_in[11];
    float* out = (float*)d_out;

    __half* feat_h;  cudaGetSymbolAddress((void**)&feat_h,  g_feat_h);
    __half* wsrc_h;  cudaGetSymbolAddress((void**)&wsrc_h,  g_wsrc_h);
    __half* wdst_h;  cudaGetSymbolAddress((void**)&wdst_h,  g_wdst_h);
    __half* wngnn_h; cudaGetSymbolAddress((void**)&wngnn_h, g_wngnn_h);
    __half* hsrc_h;  cudaGetSymbolAddress((void**)&hsrc_h,  g_hsrc_h);
    float*  hdst;    cudaGetSymbolAddress((void**)&hdst,    g_hdst);
    __half* rst_h;   cudaGetSymbolAddress((void**)&rst_h,   g_rst_h);
    int*    cnt;     cudaGetSymbolAddress((void**)&cnt,     g_cnt);

    static bool attr_set = false;
    if (!attr_set) {
        cudaFuncSetAttribute(gemm_h_kernel,
                             cudaFuncAttributeMaxDynamicSharedMemorySize,
                             128 * LDC * 4);
        attr_set = true;
    }
    const int dynsm = 128 * LDC * 4;   // 67584 (>= 4*TILE_BYTES = 40960)

    // fused feat conversion + attention logits
    feat_attn_kernel<<<1024, 256>>>(feat_src, W_attn_src, W_attn_dst);

    // weight conversions (single launch)
    {
        int tot = 2 * (HF * DD / 8) + HF * HF / 8;
        wconv_kernel<<<(tot + 255) / 256, 256>>>(W_src, W_dst, W_ngnn);
    }

    // CSR build: histogram + 3-phase parallel scan
    cudaMemsetAsync(cnt, 0, NN * sizeof(int));
    hist_kernel<<<(EE + 255) / 256, 256>>>(edge_dst);
    scan1_kernel<<<NB, 1024>>>();
    scan2_kernel<<<1, 128>>>();
    scan3_kernel<<<(NN + 255) / 256, 256>>>();

    // fused scatter + edge logits + exp
    scatter_edge_kernel<<<(EE + 255) / 256, 256>>>(edge_src, edge_dst,
                                                   feat_edge, W_attn_edge);

    // node GEMMs: h_src (fp16 out) & h_dst (fp32 + bias)
    gemm_h_kernel<<<dim3(2, (NN + 127) / 128), 256, dynsm>>>(
        feat_h, wsrc_h, wdst_h, nullptr, b_dst, nullptr,
        nullptr, hdst, hsrc_h, NN, DD, 0);

    // pull aggregation (softmax + weighted sum), warp per dst
    agg_kernel<<<(NN * 32 + 255) / 256, 256>>>();

    // NGNN GEMM + ReLU + bias + residual -> out
    gemm_h_kernel<<<dim3(1, (NN + 127) / 128), 256, dynsm>>>(
        rst_h, wngnn_h, wngnn_h, b_ngnn, b_ngnn, hdst,
        out, out, nullptr, NN, HF, 1);
}

// round 9
// speedup vs baseline: 1.0183x; 1.0183x over previous
#include <cuda_runtime.h>
#include <cuda_fp16.h>
#include <mma.h>
#include <math.h>
#include <stdint.h>

using namespace nvcuda;

#define NN 100000
#define EE 1600000
#define DD 256
#define DE 8
#define HF 128
#define NEG_SLOPE 0.2f
#define NB ((NN + 1023) / 1024)       // scan blocks = 98
#define WCONV_BLOCKS 40               // 10240 groups-of-8 / 256

// ---------------- scratch (device globals) ----------------------------------
__device__ __half  g_feat_h[(size_t)NN * DD];
__device__ __half  g_wsrc_h[HF * DD];
__device__ __half  g_wdst_h[HF * DD];
__device__ __half  g_wngnn_h[HF * HF];
__device__ __half  g_hsrc_h[(size_t)NN * HF];
__device__ float   g_hdst[(size_t)NN * HF];
__device__ __half  g_rst_h[(size_t)NN * HF];
__device__ float2  g_asrc[NN];
__device__ float2  g_adst[NN];
__device__ float2  g_ep  [EE];
__device__ int     g_cnt [NN];        // zero at load; scan1 re-zeroes each run
__device__ int     g_off [NN + 1];
__device__ int     g_cur [NN];
__device__ int     g_psrc[EE];
__device__ int     g_tmp [NN];
__device__ int     g_bsum[128];

// ---------------- phase 1: weight conv + feat fp32->fp16 + attn logits ------
static __device__ __forceinline__ float dot8(float4 x0, float4 x1,
                                             float4 w0, float4 w1) {
    float s = x0.x * w0.x;
    s = fmaf(x0.y, w0.y, s); s = fmaf(x0.z, w0.z, s); s = fmaf(x0.w, w0.w, s);
    s = fmaf(x1.x, w1.x, s); s = fmaf(x1.y, w1.y, s);
    s = fmaf(x1.z, w1.z, s); s = fmaf(x1.w, w1.w, s);
    return s;
}

__global__ void phase1_kernel(const float* __restrict__ feat,
                              const float* __restrict__ Was,
                              const float* __restrict__ Wad,
                              const float* __restrict__ Wsrc,
                              const float* __restrict__ Wdst,
                              const float* __restrict__ Wngnn) {
    if (blockIdx.x < WCONV_BLOCKS) {
        // ---- weight fp32->fp16 ----
        int i = blockIdx.x * blockDim.x + threadIdx.x;
        const int n1 = HF * DD / 8, n2 = 2 * n1, n3 = n2 + HF * HF / 8;
        const float* src;
        __half* dst;
        int k;
        if (i < n1)      { src = Wsrc;  dst = g_wsrc_h;  k = i; }
        else if (i < n2) { src = Wdst;  dst = g_wdst_h;  k = i - n1; }
        else if (i < n3) { src = Wngnn; dst = g_wngnn_h; k = i - n2; }
        else return;
        const float4* s = (const float4*)(src + (size_t)k * 8);
        float4 a = s[0], b = s[1];
        __half2 h[4] = {__floats2half2_rn(a.x, a.y), __floats2half2_rn(a.z, a.w),
                        __floats2half2_rn(b.x, b.y), __floats2half2_rn(b.z, b.w)};
        *(uint4*)(dst + (size_t)k * 8) = *(uint4*)h;
        return;
    }

    // ---- feat convert + attention logits ----
    int lane = threadIdx.x & 31;
    int warp = ((blockIdx.x - WCONV_BLOCKS) * blockDim.x + threadIdx.x) >> 5;
    int nwarps = ((gridDim.x - WCONV_BLOCKS) * blockDim.x) >> 5;
    int cb = lane * 8;

    float4 ws0a = *(const float4*)(Was + cb);
    float4 ws0b = *(const float4*)(Was + cb + 4);
    float4 ws1a = *(const float4*)(Was + DD + cb);
    float4 ws1b = *(const float4*)(Was + DD + cb + 4);
    float4 wd0a = *(const float4*)(Wad + cb);
    float4 wd0b = *(const float4*)(Wad + cb + 4);
    float4 wd1a = *(const float4*)(Wad + DD + cb);
    float4 wd1b = *(const float4*)(Wad + DD + cb + 4);

    for (int n = warp; n < NN; n += nwarps) {
        const float* fp = feat + (size_t)n * DD + cb;
        float4 x0 = *(const float4*)fp;
        float4 x1 = *(const float4*)(fp + 4);

        __half2 h[4] = {__floats2half2_rn(x0.x, x0.y),
                        __floats2half2_rn(x0.z, x0.w),
                        __floats2half2_rn(x1.x, x1.y),
                        __floats2half2_rn(x1.z, x1.w)};
        *(uint4*)(g_feat_h + (size_t)n * DD + cb) = *(uint4*)h;

        float s0 = dot8(x0, x1, ws0a, ws0b);
        float s1 = dot8(x0, x1, ws1a, ws1b);
        float d0 = dot8(x0, x1, wd0a, wd0b);
        float d1 = dot8(x0, x1, wd1a, wd1b);
#pragma unroll
        for (int off = 16; off > 0; off >>= 1) {
            s0 += __shfl_xor_sync(0xffffffff, s0, off);
            s1 += __shfl_xor_sync(0xffffffff, s1, off);
            d0 += __shfl_xor_sync(0xffffffff, d0, off);
            d1 += __shfl_xor_sync(0xffffffff, d1, off);
        }
        if (lane == 0) {
            g_asrc[n] = make_float2(s0, s1);
            g_adst[n] = make_float2(d0, d1);
        }
    }
}

// ---------------- CSR build --------------------------------------------------
__global__ void hist_kernel(const int* __restrict__ ed) {
    int i = blockIdx.x * blockDim.x + threadIdx.x;
    if (i < EE) atomicAdd(&g_cnt[ed[i]], 1);
}

// block-local exclusive scan + block sums; ALSO re-zeroes g_cnt for next run
__global__ void scan1_kernel() {
    __shared__ int sh[1024];
    int t = threadIdx.x;
    int gi = blockIdx.x * 1024 + t;
    int v = (gi < NN) ? g_cnt[gi] : 0;
    if (gi < NN) g_cnt[gi] = 0;          // self-clean for graph replay
    sh[t] = v;
    __syncthreads();
#pragma unroll
    for (int off = 1; off < 1024; off <<= 1) {
        int add = (t >= off) ? sh[t - off] : 0;
        __syncthreads();
        sh[t] += add;
        __syncthreads();
    }
    if (gi < NN) g_tmp[gi] = sh[t] - v;
    if (t == 1023) g_bsum[blockIdx.x] = sh[1023];
}

__global__ void scan2_kernel() {
    __shared__ int sh[128];
    int t = threadIdx.x;
    int v = (t < NB) ? g_bsum[t] : 0;
    sh[t] = v;
    __syncthreads();
#pragma unroll
    for (int off = 1; off < 128; off <<= 1) {
        int add = (t >= off) ? sh[t - off] : 0;
        __syncthreads();
        sh[t] += add;
        __syncthreads();
    }
    if (t < NB) g_bsum[t] = sh[t] - v;
}

__global__ void scan3_kernel() {
    int i = blockIdx.x * blockDim.x + threadIdx.x;
    if (i < NN) {
        int o = g_tmp[i] + g_bsum[i >> 10];
        g_off[i] = o;
        g_cur[i] = o;
    }
    if (i == 0) g_off[NN] = EE;
}

// ---------------- fused: CSR scatter + edge logit + leaky + exp --------------
__global__ void scatter_edge_kernel(const int* __restrict__ es,
                                    const int* __restrict__ ed,
                                    const float* __restrict__ fe,
                                    const float* __restrict__ Wae) {
    int i = blockIdx.x * blockDim.x + threadIdx.x;
    if (i >= EE) return;

    int s = es[i], d = ed[i];
    int pos = atomicAdd(&g_cur[d], 1);
    g_psrc[pos] = s;

    float4 x0 = *(const float4*)(fe + (size_t)i * DE);
    float4 x1 = *(const float4*)(fe + (size_t)i * DE + 4);

    float ae0 = x0.x * __ldg(Wae + 0) + x0.y * __ldg(Wae + 1) +
                x0.z * __ldg(Wae + 2) + x0.w * __ldg(Wae + 3) +
                x1.x * __ldg(Wae + 4) + x1.y * __ldg(Wae + 5) +
                x1.z * __ldg(Wae + 6) + x1.w * __ldg(Wae + 7);
    float ae1 = x0.x * __ldg(Wae + 8)  + x0.y * __ldg(Wae + 9) +
                x0.z * __ldg(Wae + 10) + x0.w * __ldg(Wae + 11) +
                x1.x * __ldg(Wae + 12) + x1.y * __ldg(Wae + 13) +
                x1.z * __ldg(Wae + 14) + x1.w * __ldg(Wae + 15);

    float2 as = g_asrc[s];
    float2 ad = g_adst[d];
    float e0 = as.x + ad.x + ae0;
    float e1 = as.y + ad.y + ae1;
    e0 = (e0 >= 0.f) ? e0 : NEG_SLOPE * e0;
    e1 = (e1 >= 0.f) ? e1 : NEG_SLOPE * e1;
    g_ep[pos] = make_float2(__expf(e0), __expf(e1));
}

// ---------------- tensor-core GEMM: C[*,128] = A[M,K] @ B[128,K]^T ----------
#define LDA 40
#define LDC 132
__global__ void __launch_bounds__(256)
gemm_h_kernel(const __half* __restrict__ A,
              const __half* __restrict__ B0, const __half* __restrict__ B1,
              const float* __restrict__ bias0, const float* __restrict__ bias1,
              const float* __restrict__ add,
              float* __restrict__ C0f, float* __restrict__ C1f,
              __half* __restrict__ C0h,
              int M, int K, int mode) {
    extern __shared__ char dynsm[];
    __half* As = (__half*)dynsm;
    __half* Bs = (__half*)(dynsm + 128 * LDA * 2);
    float*  Cs = (float*)dynsm;

    const __half* B    = (blockIdx.x == 0) ? B0 : B1;
    const float*  bias = (blockIdx.x == 0) ? bias0 : bias1;
    bool h_out = (blockIdx.x == 0) && (C0h != nullptr);

    int bm = blockIdx.y * 128;
    int t  = threadIdx.x;
    int w  = t >> 5;
    int wm = w & 3;
    int wn = w >> 2;

    wmma::fragment<wmma::accumulator, 16, 16, 16, float> cf[2][4];
#pragma unroll
    for (int i = 0; i < 2; i++)
#pragma unroll
        for (int j = 0; j < 4; j++) wmma::fill_fragment(cf[i][j], 0.0f);

    int lr = t >> 1;
    int lh = (t & 1) * 16;

    for (int kt = 0; kt < K; kt += 32) {
        {
            int arow = bm + lr;
            uint4 v0 = make_uint4(0, 0, 0, 0), v1 = v0;
            if (arow < M) {
                const __half* ap = A + (size_t)arow * K + kt + lh;
                v0 = *(const uint4*)ap;
                v1 = *(const uint4*)(ap + 8);
            }
            *(uint4*)&As[lr * LDA + lh] = v0;
            *(uint4*)&As[lr * LDA + lh + 8] = v1;
        }
        {
            const __half* bp = B + (size_t)lr * K + kt + lh;
            *(uint4*)&Bs[lr * LDA + lh] = *(const uint4*)bp;
            *(uint4*)&Bs[lr * LDA + lh + 8] = *(const uint4*)(bp + 8);
        }
        __syncthreads();

#pragma unroll
        for (int ks = 0; ks < 32; ks += 16) {
            wmma::fragment<wmma::matrix_a, 16, 16, 16, __half, wmma::row_major> af[2];
            wmma::fragment<wmma::matrix_b, 16, 16, 16, __half, wmma::col_major> bf[4];
#pragma unroll
            for (int i = 0; i < 2; i++)
                wmma::load_matrix_sync(af[i], &As[(wm * 32 + i * 16) * LDA + ks], LDA);
#pragma unroll
            for (int j = 0; j < 4; j++)
                wmma::load_matrix_sync(bf[j], &Bs[(wn * 64 + j * 16) * LDA + ks], LDA);
#pragma unroll
            for (int i = 0; i < 2; i++)
#pragma unroll
                for (int j = 0; j < 4; j++)
                    wmma::mma_sync(cf[i][j], af[i], bf[j], cf[i][j]);
        }
        __syncthreads();
    }

#pragma unroll
    for (int i = 0; i < 2; i++)
#pragma unroll
        for (int j = 0; j < 4; j++)
            wmma::store_matrix_sync(&Cs[(wm * 32 + i * 16) * LDC + wn * 64 + j * 16],
                                    cf[i][j], LDC, wmma::mem_row_major);
    __syncthreads();

    {
        int r = t >> 1;
        int cb = (t & 1) * 64;
        int row = bm + r;
        if (row < M) {
#pragma unroll
            for (int j = 0; j < 64; j += 4) {
                float4 v = *(float4*)&Cs[r * LDC + cb + j];
                if (bias) {
                    float4 b = *(const float4*)(bias + cb + j);
                    v.x += b.x; v.y += b.y; v.z += b.z; v.w += b.w;
                }
                if (mode == 1) {
                    float4 rs = *(const float4*)(add + (size_t)row * HF + cb + j);
                    v.x = fmaxf(v.x, 0.f) + rs.x;
                    v.y = fmaxf(v.y, 0.f) + rs.y;
                    v.z = fmaxf(v.z, 0.f) + rs.z;
                    v.w = fmaxf(v.w, 0.f) + rs.w;
                }
                if (h_out) {
                    __half2 p[2] = {__floats2half2_rn(v.x, v.y),
                                    __floats2half2_rn(v.z, v.w)};
                    *(uint2*)(C0h + (size_t)row * HF + cb + j) = *(uint2*)p;
                } else {
                    float* Cf = (blockIdx.x == 0) ? C0f : C1f;
                    *(float4*)(Cf + (size_t)row * HF + cb + j) = v;
                }
            }
        }
    }
}

// ---------------- pull aggregation: single pass, warp per dst node -----------
__global__ void agg_kernel() {
    int warp = (blockIdx.x * blockDim.x + threadIdx.x) >> 5;
    if (warp >= NN) return;
    int lane = threadIdx.x & 31;

    int row = g_off[warp];
    int end = g_off[warp + 1];

    const int elem = lane * 4;        // lanes 0..15 head0, 16..31 head1
    const bool h0 = (lane < 16);
    float z = 0.f;
    float a0 = 0.f, a1 = 0.f, a2 = 0.f, a3 = 0.f;

    int j = row;
    for (; j + 2 <= end; j += 2) {
        float2 e0 = g_ep[j];
        float2 e1 = g_ep[j + 1];
        int s0 = g_psrc[j];
        int s1 = g_psrc[j + 1];
        float c0 = h0 ? e0.x : e0.y;
        float c1 = h0 ? e1.x : e1.y;
        z += c0 + c1;
        const __half2* p0 = (const __half2*)(g_hsrc_h + (size_t)s0 * HF + elem);
        const __half2* p1 = (const __half2*)(g_hsrc_h + (size_t)s1 * HF + elem);
        __half2 u0 = p0[0], u1 = p0[1];
        __half2 v0 = p1[0], v1 = p1[1];
        float2 fu0 = __half22float2(u0), fu1 = __half22float2(u1);
        float2 fv0 = __half22float2(v0), fv1 = __half22float2(v1);
        a0 = fmaf(fu0.x, c0, a0); a1 = fmaf(fu0.y, c0, a1);
        a2 = fmaf(fu1.x, c0, a2); a3 = fmaf(fu1.y, c0, a3);
        a0 = fmaf(fv0.x, c1, a0); a1 = fmaf(fv0.y, c1, a1);
        a2 = fmaf(fv1.x, c1, a2); a3 = fmaf(fv1.y, c1, a3);
    }
    if (j < end) {
        float2 e0 = g_ep[j];
        int s0 = g_psrc[j];
        float c0 = h0 ? e0.x : e0.y;
        z += c0;
        const __half2* p0 = (const __half2*)(g_hsrc_h + (size_t)s0 * HF + elem);
        __half2 u0 = p0[0], u1 = p0[1];
        float2 fu0 = __half22float2(u0), fu1 = __half22float2(u1);
        a0 = fmaf(fu0.x, c0, a0); a1 = fmaf(fu0.y, c0, a1);
        a2 = fmaf(fu1.x, c0, a2); a3 = fmaf(fu1.y, c0, a3);
    }

    float invz = (end > row) ? __fdividef(1.f, z) : 0.f;
    __half2 hh[2] = {__floats2half2_rn(a0 * invz, a1 * invz),
                     __floats2half2_rn(a2 * invz, a3 * invz)};
    *(uint2*)(g_rst_h + (size_t)warp * HF + elem) = *(uint2*)hh;
}

// ---------------- launch -----------------------------------------------------
extern "C" void kernel_launch(void* const* d_in, const int* in_sizes, int n_in,
                              void* d_out, int out_size) {
    const float* feat_src    = (const float*)d_in[0];
    const float* feat_edge   = (const float*)d_in[1];
    const int*   edge_src    = (const int*)d_in[2];
    const int*   edge_dst    = (const int*)d_in[3];
    const float* W_src       = (const float*)d_in[4];
    const float* W_dst       = (const float*)d_in[5];
    const float* b_dst       = (const float*)d_in[6];
    const float* W_attn_src  = (const float*)d_in[7];
    const float* W_attn_dst  = (const float*)d_in[8];
    const float* W_attn_edge = (const float*)d_in[9];
    const float* W_ngnn      = (const float*)d_in[10];
    const float* b_ngnn      = (const float*)d_in[11];
    float* out = (float*)d_out;

    __half* feat_h;  cudaGetSymbolAddress((void**)&feat_h,  g_feat_h);
    __half* wsrc_h;  cudaGetSymbolAddress((void**)&wsrc_h,  g_wsrc_h);
    __half* wdst_h;  cudaGetSymbolAddress((void**)&wdst_h,  g_wdst_h);
    __half* wngnn_h; cudaGetSymbolAddress((void**)&wngnn_h, g_wngnn_h);
    __half* hsrc_h;  cudaGetSymbolAddress((void**)&hsrc_h,  g_hsrc_h);
    float*  hdst;    cudaGetSymbolAddress((void**)&hdst,    g_hdst);
    __half* rst_h;   cudaGetSymbolAddress((void**)&rst_h,   g_rst_h);

    static bool attr_set = false;
    if (!attr_set) {
        cudaFuncSetAttribute(gemm_h_kernel,
                             cudaFuncAttributeMaxDynamicSharedMemorySize,
                             128 * LDC * 4);
        attr_set = true;
    }
    const int dynsm = 128 * LDC * 4;

    // 1: weights + feat conversion + attention logits
    phase1_kernel<<<WCONV_BLOCKS + 1024, 256>>>(feat_src, W_attn_src, W_attn_dst,
                                                W_src, W_dst, W_ngnn);
    // 2-4: CSR histogram + scan (scan1 self-cleans g_cnt)
    hist_kernel<<<(EE + 255) / 256, 256>>>(edge_dst);
    scan1_kernel<<<NB, 1024>>>();
    scan2_kernel<<<1, 128>>>();

    // 5: node GEMMs (h_src fp16, h_dst fp32+bias) — launch #5 for ncu capture
    gemm_h_kernel<<<dim3(2, (NN + 127) / 128), 256, dynsm>>>(
        feat_h, wsrc_h, wdst_h, nullptr, b_dst, nullptr,
        nullptr, hdst, hsrc_h, NN, DD, 0);

    // 6: finish CSR offsets
    scan3_kernel<<<(NN + 255) / 256, 256>>>();

    // 7: fused scatter + edge logits + exp
    scatter_edge_kernel<<<(EE + 255) / 256, 256>>>(edge_src, edge_dst,
                                                   feat_edge, W_attn_edge);

    // 8: pull aggregation (single-pass softmax + weighted sum)
    agg_kernel<<<(NN * 32 + 255) / 256, 256>>>();

    // 9: NGNN GEMM + ReLU + bias + residual -> out
    gemm_h_kernel<<<dim3(1, (NN + 127) / 128), 256, dynsm>>>(
        rst_h, wngnn_h, wngnn_h, b_ngnn, b_ngnn, hdst,
        out, out, nullptr, NN, HF, 1);
}

// round 11
// speedup vs baseline: 1.0393x; 1.0206x over previous
#include <cuda_runtime.h>
#include <cuda_fp16.h>
#include <mma.h>
#include <math.h>
#include <stdint.h>

using namespace nvcuda;

#define NN 100000
#define EE 1600000
#define DD 256
#define DE 8
#define HF 128
#define NEG_SLOPE 0.2f
#define NB ((NN + 1023) / 1024)       // scan blocks = 98
#define WCONV_BLOCKS 40
#define HIST_BLOCKS ((EE + 255) / 256)

// ---------------- scratch (device globals) ----------------------------------
__device__ __half  g_feat_h[(size_t)NN * DD];
__device__ __half  g_wsrc_h[HF * DD];
__device__ __half  g_wdst_h[HF * DD];
__device__ __half  g_wngnn_h[HF * HF];
__device__ __half  g_hsrc_h[(size_t)NN * HF];
__device__ __half  g_hdst_h[(size_t)NN * HF];   // fp16 residual branch
__device__ __half  g_rst_h[(size_t)NN * HF];
__device__ float2  g_asrc[NN];
__device__ float2  g_adst[NN];
__device__ float2  g_ep  [EE];
__device__ int     g_cnt [NN];        // zero at load; scan1 self-cleans
__device__ int     g_off [NN + 1];
__device__ int     g_cur [NN];
__device__ int     g_psrc[EE];
__device__ int     g_tmp [NN];
__device__ int     g_bsum[128];

// ---------------- phase 1: wconv + hist + feat f2h + attn logits -------------
static __device__ __forceinline__ float dot8(float4 x0, float4 x1,
                                             float4 w0, float4 w1) {
    float s = x0.x * w0.x;
    s = fmaf(x0.y, w0.y, s); s = fmaf(x0.z, w0.z, s); s = fmaf(x0.w, w0.w, s);
    s = fmaf(x1.x, w1.x, s); s = fmaf(x1.y, w1.y, s);
    s = fmaf(x1.z, w1.z, s); s = fmaf(x1.w, w1.w, s);
    return s;
}

__global__ void phase1_kernel(const float* __restrict__ feat,
                              const float* __restrict__ Was,
                              const float* __restrict__ Wad,
                              const float* __restrict__ Wsrc,
                              const float* __restrict__ Wdst,
                              const float* __restrict__ Wngnn,
                              const int* __restrict__ ed) {
    if (blockIdx.x < WCONV_BLOCKS) {
        int i = blockIdx.x * blockDim.x + threadIdx.x;
        const int n1 = HF * DD / 8, n2 = 2 * n1, n3 = n2 + HF * HF / 8;
        const float* src;
        __half* dst;
        int k;
        if (i < n1)      { src = Wsrc;  dst = g_wsrc_h;  k = i; }
        else if (i < n2) { src = Wdst;  dst = g_wdst_h;  k = i - n1; }
        else if (i < n3) { src = Wngnn; dst = g_wngnn_h; k = i - n2; }
        else return;
        const float4* s = (const float4*)(src + (size_t)k * 8);
        float4 a = s[0], b = s[1];
        __half2 h[4] = {__floats2half2_rn(a.x, a.y), __floats2half2_rn(a.z, a.w),
                        __floats2half2_rn(b.x, b.y), __floats2half2_rn(b.z, b.w)};
        *(uint4*)(dst + (size_t)k * 8) = *(uint4*)h;
        return;
    }
    if (blockIdx.x < WCONV_BLOCKS + HIST_BLOCKS) {
        int i = (blockIdx.x - WCONV_BLOCKS) * blockDim.x + threadIdx.x;
        if (i < EE) atomicAdd(&g_cnt[ed[i]], 1);
        return;
    }

    // ---- feat convert + attention logits ----
    int lane = threadIdx.x & 31;
    int base = WCONV_BLOCKS + HIST_BLOCKS;
    int warp = ((blockIdx.x - base) * blockDim.x + threadIdx.x) >> 5;
    int nwarps = ((gridDim.x - base) * blockDim.x) >> 5;
    int cb = lane * 8;

    float4 ws0a = *(const float4*)(Was + cb);
    float4 ws0b = *(const float4*)(Was + cb + 4);
    float4 ws1a = *(const float4*)(Was + DD + cb);
    float4 ws1b = *(const float4*)(Was + DD + cb + 4);
    float4 wd0a = *(const float4*)(Wad + cb);
    float4 wd0b = *(const float4*)(Wad + cb + 4);
    float4 wd1a = *(const float4*)(Wad + DD + cb);
    float4 wd1b = *(const float4*)(Wad + DD + cb + 4);

    for (int n = warp; n < NN; n += nwarps) {
        const float* fp = feat + (size_t)n * DD + cb;
        float4 x0 = *(const float4*)fp;
        float4 x1 = *(const float4*)(fp + 4);

        __half2 h[4] = {__floats2half2_rn(x0.x, x0.y),
                        __floats2half2_rn(x0.z, x0.w),
                        __floats2half2_rn(x1.x, x1.y),
                        __floats2half2_rn(x1.z, x1.w)};
        *(uint4*)(g_feat_h + (size_t)n * DD + cb) = *(uint4*)h;

        float s0 = dot8(x0, x1, ws0a, ws0b);
        float s1 = dot8(x0, x1, ws1a, ws1b);
        float d0 = dot8(x0, x1, wd0a, wd0b);
        float d1 = dot8(x0, x1, wd1a, wd1b);
#pragma unroll
        for (int off = 16; off > 0; off >>= 1) {
            s0 += __shfl_xor_sync(0xffffffff, s0, off);
            s1 += __shfl_xor_sync(0xffffffff, s1, off);
            d0 += __shfl_xor_sync(0xffffffff, d0, off);
            d1 += __shfl_xor_sync(0xffffffff, d1, off);
        }
        if (lane == 0) {
            g_asrc[n] = make_float2(s0, s1);
            g_adst[n] = make_float2(d0, d1);
        }
    }
}

// ---------------- CSR scan ----------------------------------------------------
__global__ void scan1_kernel() {
    __shared__ int sh[1024];
    int t = threadIdx.x;
    int gi = blockIdx.x * 1024 + t;
    int v = (gi < NN) ? g_cnt[gi] : 0;
    if (gi < NN) g_cnt[gi] = 0;          // self-clean for graph replay
    sh[t] = v;
    __syncthreads();
#pragma unroll
    for (int off = 1; off < 1024; off <<= 1) {
        int add = (t >= off) ? sh[t - off] : 0;
        __syncthreads();
        sh[t] += add;
        __syncthreads();
    }
    if (gi < NN) g_tmp[gi] = sh[t] - v;
    if (t == 1023) g_bsum[blockIdx.x] = sh[1023];
}

__global__ void scan2_kernel() {
    __shared__ int sh[128];
    int t = threadIdx.x;
    int v = (t < NB) ? g_bsum[t] : 0;
    sh[t] = v;
    __syncthreads();
#pragma unroll
    for (int off = 1; off < 128; off <<= 1) {
        int add = (t >= off) ? sh[t - off] : 0;
        __syncthreads();
        sh[t] += add;
        __syncthreads();
    }
    if (t < NB) g_bsum[t] = sh[t] - v;
}

__global__ void scan3_kernel() {
    int i = blockIdx.x * blockDim.x + threadIdx.x;
    if (i < NN) {
        int o = g_tmp[i] + g_bsum[i >> 10];
        g_off[i] = o;
        g_cur[i] = o;
    }
    if (i == 0) g_off[NN] = EE;
}

// ---------------- fused: CSR scatter + edge logit + leaky + exp --------------
__global__ void scatter_edge_kernel(const int* __restrict__ es,
                                    const int* __restrict__ ed,
                                    const float* __restrict__ fe,
                                    const float* __restrict__ Wae) {
    int i = blockIdx.x * blockDim.x + threadIdx.x;
    if (i >= EE) return;

    int s = es[i], d = ed[i];
    int pos = atomicAdd(&g_cur[d], 1);
    g_psrc[pos] = s;

    float4 x0 = *(const float4*)(fe + (size_t)i * DE);
    float4 x1 = *(const float4*)(fe + (size_t)i * DE + 4);

    float ae0 = x0.x * __ldg(Wae + 0) + x0.y * __ldg(Wae + 1) +
                x0.z * __ldg(Wae + 2) + x0.w * __ldg(Wae + 3) +
                x1.x * __ldg(Wae + 4) + x1.y * __ldg(Wae + 5) +
                x1.z * __ldg(Wae + 6) + x1.w * __ldg(Wae + 7);
    float ae1 = x0.x * __ldg(Wae + 8)  + x0.y * __ldg(Wae + 9) +
                x0.z * __ldg(Wae + 10) + x0.w * __ldg(Wae + 11) +
                x1.x * __ldg(Wae + 12) + x1.y * __ldg(Wae + 13) +
                x1.z * __ldg(Wae + 14) + x1.w * __ldg(Wae + 15);

    float2 as = g_asrc[s];
    float2 ad = g_adst[d];
    float e0 = as.x + ad.x + ae0;
    float e1 = as.y + ad.y + ae1;
    e0 = (e0 >= 0.f) ? e0 : NEG_SLOPE * e0;
    e1 = (e1 >= 0.f) ? e1 : NEG_SLOPE * e1;
    g_ep[pos] = make_float2(__expf(e0), __expf(e1));
}

// ---------------- wmma GEMM: C[*,128] = A[M,K] @ B[128,K]^T ------------------
// mode 0: Ch = half(acc + bias)            (both col-blocks write half)
// mode 1: Cf = relu(acc + bias) + half2float(add)    (fp32 out)
#define LDA 40
#define LDC 132
__global__ void __launch_bounds__(256)
gemm_h_kernel(const __half* __restrict__ A,
              const __half* __restrict__ B0, const __half* __restrict__ B1,
              const float* __restrict__ bias0, const float* __restrict__ bias1,
              const __half* __restrict__ add,
              float* __restrict__ Cf,
              __half* __restrict__ C0h, __half* __restrict__ C1h,
              int M, int K, int mode) {
    extern __shared__ char dynsm[];
    __half* As = (__half*)dynsm;
    __half* Bs = (__half*)(dynsm + 128 * LDA * 2);
    float*  Cs = (float*)dynsm;

    const __half* B    = (blockIdx.x == 0) ? B0 : B1;
    const float*  bias = (blockIdx.x == 0) ? bias0 : bias1;
    __half*       Ch   = (blockIdx.x == 0) ? C0h : C1h;

    int bm = blockIdx.y * 128;
    int t  = threadIdx.x;
    int w  = t >> 5;
    int wm = w & 3;
    int wn = w >> 2;

    wmma::fragment<wmma::accumulator, 16, 16, 16, float> cf[2][4];
#pragma unroll
    for (int i = 0; i < 2; i++)
#pragma unroll
        for (int j = 0; j < 4; j++) wmma::fill_fragment(cf[i][j], 0.0f);

    int lr = t >> 1;
    int lh = (t & 1) * 16;

    for (int kt = 0; kt < K; kt += 32) {
        {
            int arow = bm + lr;
            uint4 v0 = make_uint4(0, 0, 0, 0), v1 = v0;
            if (arow < M) {
                const __half* ap = A + (size_t)arow * K + kt + lh;
                v0 = *(const uint4*)ap;
                v1 = *(const uint4*)(ap + 8);
            }
            *(uint4*)&As[lr * LDA + lh] = v0;
            *(uint4*)&As[lr * LDA + lh + 8] = v1;
        }
        {
            const __half* bp = B + (size_t)lr * K + kt + lh;
            *(uint4*)&Bs[lr * LDA + lh] = *(const uint4*)bp;
            *(uint4*)&Bs[lr * LDA + lh + 8] = *(const uint4*)(bp + 8);
        }
        __syncthreads();

#pragma unroll
        for (int ks = 0; ks < 32; ks += 16) {
            wmma::fragment<wmma::matrix_a, 16, 16, 16, __half, wmma::row_major> af[2];
            wmma::fragment<wmma::matrix_b, 16, 16, 16, __half, wmma::col_major> bf[4];
#pragma unroll
            for (int i = 0; i < 2; i++)
                wmma::load_matrix_sync(af[i], &As[(wm * 32 + i * 16) * LDA + ks], LDA);
#pragma unroll
            for (int j = 0; j < 4; j++)
                wmma::load_matrix_sync(bf[j], &Bs[(wn * 64 + j * 16) * LDA + ks], LDA);
#pragma unroll
            for (int i = 0; i < 2; i++)
#pragma unroll
                for (int j = 0; j < 4; j++)
                    wmma::mma_sync(cf[i][j], af[i], bf[j], cf[i][j]);
        }
        __syncthreads();
    }

#pragma unroll
    for (int i = 0; i < 2; i++)
#pragma unroll
        for (int j = 0; j < 4; j++)
            wmma::store_matrix_sync(&Cs[(wm * 32 + i * 16) * LDC + wn * 64 + j * 16],
                                    cf[i][j], LDC, wmma::mem_row_major);
    __syncthreads();

    {
        int r = t >> 1;
        int cb = (t & 1) * 64;
        int row = bm + r;
        if (row < M) {
#pragma unroll
            for (int j = 0; j < 64; j += 4) {
                float4 v = *(float4*)&Cs[r * LDC + cb + j];
                if (bias) {
                    float4 b = *(const float4*)(bias + cb + j);
                    v.x += b.x; v.y += b.y; v.z += b.z; v.w += b.w;
                }
                if (mode == 1) {
                    uint2 ru = *(const uint2*)(add + (size_t)row * HF + cb + j);
                    __half2* rh = (__half2*)&ru;
                    float2 r0 = __half22float2(rh[0]);
                    float2 r1 = __half22float2(rh[1]);
                    v.x = fmaxf(v.x, 0.f) + r0.x;
                    v.y = fmaxf(v.y, 0.f) + r0.y;
                    v.z = fmaxf(v.z, 0.f) + r1.x;
                    v.w = fmaxf(v.w, 0.f) + r1.y;
                    *(float4*)(Cf + (size_t)row * HF + cb + j) = v;
                } else {
                    __half2 p[2] = {__floats2half2_rn(v.x, v.y),
                                    __floats2half2_rn(v.z, v.w)};
                    *(uint2*)(Ch + (size_t)row * HF + cb + j) = *(uint2*)p;
                }
            }
        }
    }
}

// ---------------- pull aggregation: single pass, warp per dst node -----------
__global__ void agg_kernel() {
    int warp = (blockIdx.x * blockDim.x + threadIdx.x) >> 5;
    if (warp >= NN) return;
    int lane = threadIdx.x & 31;

    int row = g_off[warp];
    int end = g_off[warp + 1];

    const int elem = lane * 4;
    const bool h0 = (lane < 16);
    float z = 0.f;
    float a0 = 0.f, a1 = 0.f, a2 = 0.f, a3 = 0.f;

    int j = row;
    for (; j + 2 <= end; j += 2) {
        float2 e0 = g_ep[j];
        float2 e1 = g_ep[j + 1];
        int s0 = g_psrc[j];
        int s1 = g_psrc[j + 1];
        float c0 = h0 ? e0.x : e0.y;
        float c1 = h0 ? e1.x : e1.y;
        z += c0 + c1;
        const __half2* p0 = (const __half2*)(g_hsrc_h + (size_t)s0 * HF + elem);
        const __half2* p1 = (const __half2*)(g_hsrc_h + (size_t)s1 * HF + elem);
        __half2 u0 = p0[0], u1 = p0[1];
        __half2 v0 = p1[0], v1 = p1[1];
        float2 fu0 = __half22float2(u0), fu1 = __half22float2(u1);
        float2 fv0 = __half22float2(v0), fv1 = __half22float2(v1);
        a0 = fmaf(fu0.x, c0, a0); a1 = fmaf(fu0.y, c0, a1);
        a2 = fmaf(fu1.x, c0, a2); a3 = fmaf(fu1.y, c0, a3);
        a0 = fmaf(fv0.x, c1, a0); a1 = fmaf(fv0.y, c1, a1);
        a2 = fmaf(fv1.x, c1, a2); a3 = fmaf(fv1.y, c1, a3);
    }
    if (j < end) {
        float2 e0 = g_ep[j];
        int s0 = g_psrc[j];
        float c0 = h0 ? e0.x : e0.y;
        z += c0;
        const __half2* p0 = (const __half2*)(g_hsrc_h + (size_t)s0 * HF + elem);
        __half2 u0 = p0[0], u1 = p0[1];
        float2 fu0 = __half22float2(u0), fu1 = __half22float2(u1);
        a0 = fmaf(fu0.x, c0, a0); a1 = fmaf(fu0.y, c0, a1);
        a2 = fmaf(fu1.x, c0, a2); a3 = fmaf(fu1.y, c0, a3);
    }

    float invz = (end > row) ? __fdividef(1.f, z) : 0.f;
    __half2 hh[2] = {__floats2half2_rn(a0 * invz, a1 * invz),
                     __floats2half2_rn(a2 * invz, a3 * invz)};
    *(uint2*)(g_rst_h + (size_t)warp * HF + elem) = *(uint2*)hh;
}

// ---------------- launch -----------------------------------------------------
extern "C" void kernel_launch(void* const* d_in, const int* in_sizes, int n_in,
                              void* d_out, int out_size) {
    const float* feat_src    = (const float*)d_in[0];
    const float* feat_edge   = (const float*)d_in[1];
    const int*   edge_src    = (const int*)d_in[2];
    const int*   edge_dst    = (const int*)d_in[3];
    const float* W_src       = (const float*)d_in[4];
    const float* W_dst       = (const float*)d_in[5];
    const float* b_dst       = (const float*)d_in[6];
    const float* W_attn_src  = (const float*)d_in[7];
    const float* W_attn_dst  = (const float*)d_in[8];
    const float* W_attn_edge = (const float*)d_in[9];
    const float* W_ngnn      = (const float*)d_in[10];
    const float* b_ngnn      = (const float*)d_in[11];
    float* out = (float*)d_out;

    __half* feat_h;  cudaGetSymbolAddress((void**)&feat_h,  g_feat_h);
    __half* wsrc_h;  cudaGetSymbolAddress((void**)&wsrc_h,  g_wsrc_h);
    __half* wdst_h;  cudaGetSymbolAddress((void**)&wdst_h,  g_wdst_h);
    __half* wngnn_h; cudaGetSymbolAddress((void**)&wngnn_h, g_wngnn_h);
    __half* hsrc_h;  cudaGetSymbolAddress((void**)&hsrc_h,  g_hsrc_h);
    __half* hdst_h;  cudaGetSymbolAddress((void**)&hdst_h,  g_hdst_h);
    __half* rst_h;   cudaGetSymbolAddress((void**)&rst_h,   g_rst_h);

    static bool attr_set = false;
    if (!attr_set) {
        cudaFuncSetAttribute(gemm_h_kernel,
                             cudaFuncAttributeMaxDynamicSharedMemorySize,
                             128 * LDC * 4);
        attr_set = true;
    }
    const int dynsm = 128 * LDC * 4;

    // 0: weights + histogram + feat conversion + attention logits
    phase1_kernel<<<WCONV_BLOCKS + HIST_BLOCKS + 1024, 256>>>(
        feat_src, W_attn_src, W_attn_dst, W_src, W_dst, W_ngnn, edge_dst);

    // 1-2: CSR scan (scan1 self-cleans g_cnt)
    scan1_kernel<<<NB, 1024>>>();
    scan2_kernel<<<1, 128>>>();

    // 3: node GEMMs (h_src & h_dst fp16) — profiled slot
    gemm_h_kernel<<<dim3(2, (NN + 127) / 128), 256, dynsm>>>(
        feat_h, wsrc_h, wdst_h, nullptr, b_dst, nullptr,
        nullptr, hsrc_h, hdst_h, NN, DD, 0);

    // 4: finish CSR offsets
    scan3_kernel<<<(NN + 255) / 256, 256>>>();

    // 5: fused scatter + edge logits + exp
    scatter_edge_kernel<<<(EE + 255) / 256, 256>>>(edge_src, edge_dst,
                                                   feat_edge, W_attn_edge);

    // 6: pull aggregation (single-pass softmax + weighted sum)
    agg_kernel<<<(NN * 32 + 255) / 256, 256>>>();

    // 7: NGNN GEMM + ReLU + bias + fp16 residual -> fp32 out
    gemm_h_kernel<<<dim3(1, (NN + 127) / 128), 256, dynsm>>>(
        rst_h, wngnn_h, wngnn_h, b_ngnn, b_ngnn, hdst_h,
        out, nullptr, nullptr, NN, HF, 1);
}

// round 12
// speedup vs baseline: 1.1043x; 1.0625x over previous
#include <cuda_runtime.h>
#include <cuda_fp16.h>
#include <mma.h>
#include <math.h>
#include <stdint.h>

using namespace nvcuda;

#define NN 100000
#define EE 1600000
#define DD 256
#define DE 8
#define HF 128
#define NEG_SLOPE 0.2f
#define NB ((NN + 1023) / 1024)
#define WCONV_BLOCKS 40
#define HIST_BLOCKS ((EE + 255) / 256)

// ---------------- scratch (device globals) ----------------------------------
__device__ __half  g_feat_h[(size_t)NN * DD];
__device__ __half  g_wsrc_h[HF * DD];
__device__ __half  g_wdst_h[HF * DD];
__device__ __half  g_wngnn_h[HF * HF];
__device__ __half  g_hsrc_h[(size_t)NN * HF];
__device__ __half  g_hdst_h[(size_t)NN * HF];
__device__ __half  g_rst_h[(size_t)NN * HF];
__device__ float2  g_asrc[NN];
__device__ float2  g_adst[NN];
__device__ float2  g_ep  [EE];
__device__ int     g_cnt [NN];
__device__ int     g_off [NN + 1];
__device__ int     g_cur [NN];
__device__ int     g_psrc[EE];
__device__ int     g_tmp [NN];
__device__ int     g_bsum[128];

// ---------------- cp.async helpers (.cg = bypass L1) --------------------------
static __device__ __forceinline__ void cp16cg(__half* s, const __half* g, bool pred) {
    unsigned sa = (unsigned)__cvta_generic_to_shared(s);
    int sz = pred ? 16 : 0;
    asm volatile("cp.async.cg.shared.global [%0], [%1], 16, %2;"
                 :: "r"(sa), "l"(g), "r"(sz));
}
static __device__ __forceinline__ void cp_commit() {
    asm volatile("cp.async.commit_group;" ::: "memory");
}
template <int N>
static __device__ __forceinline__ void cp_wait() {
    asm volatile("cp.async.wait_group %0;" :: "n"(N) : "memory");
}

// ---------------- phase 1: wconv + hist + feat f2h + attn logits -------------
static __device__ __forceinline__ float dot8(float4 x0, float4 x1,
                                             float4 w0, float4 w1) {
    float s = x0.x * w0.x;
    s = fmaf(x0.y, w0.y, s); s = fmaf(x0.z, w0.z, s); s = fmaf(x0.w, w0.w, s);
    s = fmaf(x1.x, w1.x, s); s = fmaf(x1.y, w1.y, s);
    s = fmaf(x1.z, w1.z, s); s = fmaf(x1.w, w1.w, s);
    return s;
}

__global__ void phase1_kernel(const float* __restrict__ feat,
                              const float* __restrict__ Was,
                              const float* __restrict__ Wad,
                              const float* __restrict__ Wsrc,
                              const float* __restrict__ Wdst,
                              const float* __restrict__ Wngnn,
                              const int* __restrict__ ed) {
    if (blockIdx.x < WCONV_BLOCKS) {
        int i = blockIdx.x * blockDim.x + threadIdx.x;
        const int n1 = HF * DD / 8, n2 = 2 * n1, n3 = n2 + HF * HF / 8;
        const float* src;
        __half* dst;
        int k;
        if (i < n1)      { src = Wsrc;  dst = g_wsrc_h;  k = i; }
        else if (i < n2) { src = Wdst;  dst = g_wdst_h;  k = i - n1; }
        else if (i < n3) { src = Wngnn; dst = g_wngnn_h; k = i - n2; }
        else return;
        const float4* s = (const float4*)(src + (size_t)k * 8);
        float4 a = s[0], b = s[1];
        __half2 h[4] = {__floats2half2_rn(a.x, a.y), __floats2half2_rn(a.z, a.w),
                        __floats2half2_rn(b.x, b.y), __floats2half2_rn(b.z, b.w)};
        *(uint4*)(dst + (size_t)k * 8) = *(uint4*)h;
        return;
    }
    if (blockIdx.x < WCONV_BLOCKS + HIST_BLOCKS) {
        int i = (blockIdx.x - WCONV_BLOCKS) * blockDim.x + threadIdx.x;
        if (i < EE) atomicAdd(&g_cnt[ed[i]], 1);
        return;
    }

    int lane = threadIdx.x & 31;
    int base = WCONV_BLOCKS + HIST_BLOCKS;
    int warp = ((blockIdx.x - base) * blockDim.x + threadIdx.x) >> 5;
    int nwarps = ((gridDim.x - base) * blockDim.x) >> 5;
    int cb = lane * 8;

    float4 ws0a = *(const float4*)(Was + cb);
    float4 ws0b = *(const float4*)(Was + cb + 4);
    float4 ws1a = *(const float4*)(Was + DD + cb);
    float4 ws1b = *(const float4*)(Was + DD + cb + 4);
    float4 wd0a = *(const float4*)(Wad + cb);
    float4 wd0b = *(const float4*)(Wad + cb + 4);
    float4 wd1a = *(const float4*)(Wad + DD + cb);
    float4 wd1b = *(const float4*)(Wad + DD + cb + 4);

    for (int n = warp; n < NN; n += nwarps) {
        const float* fp = feat + (size_t)n * DD + cb;
        float4 x0 = *(const float4*)fp;
        float4 x1 = *(const float4*)(fp + 4);

        __half2 h[4] = {__floats2half2_rn(x0.x, x0.y),
                        __floats2half2_rn(x0.z, x0.w),
                        __floats2half2_rn(x1.x, x1.y),
                        __floats2half2_rn(x1.z, x1.w)};
        *(uint4*)(g_feat_h + (size_t)n * DD + cb) = *(uint4*)h;

        float s0 = dot8(x0, x1, ws0a, ws0b);
        float s1 = dot8(x0, x1, ws1a, ws1b);
        float d0 = dot8(x0, x1, wd0a, wd0b);
        float d1 = dot8(x0, x1, wd1a, wd1b);
#pragma unroll
        for (int off = 16; off > 0; off >>= 1) {
            s0 += __shfl_xor_sync(0xffffffff, s0, off);
            s1 += __shfl_xor_sync(0xffffffff, s1, off);
            d0 += __shfl_xor_sync(0xffffffff, d0, off);
            d1 += __shfl_xor_sync(0xffffffff, d1, off);
        }
        if (lane == 0) {
            g_asrc[n] = make_float2(s0, s1);
            g_adst[n] = make_float2(d0, d1);
        }
    }
}

// ---------------- CSR scan ----------------------------------------------------
__global__ void scan1_kernel() {
    __shared__ int sh[1024];
    int t = threadIdx.x;
    int gi = blockIdx.x * 1024 + t;
    int v = (gi < NN) ? g_cnt[gi] : 0;
    if (gi < NN) g_cnt[gi] = 0;
    sh[t] = v;
    __syncthreads();
#pragma unroll
    for (int off = 1; off < 1024; off <<= 1) {
        int add = (t >= off) ? sh[t - off] : 0;
        __syncthreads();
        sh[t] += add;
        __syncthreads();
    }
    if (gi < NN) g_tmp[gi] = sh[t] - v;
    if (t == 1023) g_bsum[blockIdx.x] = sh[1023];
}

__global__ void scan2_kernel() {
    __shared__ int sh[128];
    int t = threadIdx.x;
    int v = (t < NB) ? g_bsum[t] : 0;
    sh[t] = v;
    __syncthreads();
#pragma unroll
    for (int off = 1; off < 128; off <<= 1) {
        int add = (t >= off) ? sh[t - off] : 0;
        __syncthreads();
        sh[t] += add;
        __syncthreads();
    }
    if (t < NB) g_bsum[t] = sh[t] - v;
}

__global__ void scan3_kernel() {
    int i = blockIdx.x * blockDim.x + threadIdx.x;
    if (i < NN) {
        int o = g_tmp[i] + g_bsum[i >> 10];
        g_off[i] = o;
        g_cur[i] = o;
    }
    if (i == 0) g_off[NN] = EE;
}

// ---------------- fused: CSR scatter + edge logit + leaky + exp --------------
__global__ void scatter_edge_kernel(const int* __restrict__ es,
                                    const int* __restrict__ ed,
                                    const float* __restrict__ fe,
                                    const float* __restrict__ Wae) {
    int i = blockIdx.x * blockDim.x + threadIdx.x;
    if (i >= EE) return;

    int s = es[i], d = ed[i];
    int pos = atomicAdd(&g_cur[d], 1);
    g_psrc[pos] = s;

    float4 x0 = *(const float4*)(fe + (size_t)i * DE);
    float4 x1 = *(const float4*)(fe + (size_t)i * DE + 4);

    float ae0 = x0.x * __ldg(Wae + 0) + x0.y * __ldg(Wae + 1) +
                x0.z * __ldg(Wae + 2) + x0.w * __ldg(Wae + 3) +
                x1.x * __ldg(Wae + 4) + x1.y * __ldg(Wae + 5) +
                x1.z * __ldg(Wae + 6) + x1.w * __ldg(Wae + 7);
    float ae1 = x0.x * __ldg(Wae + 8)  + x0.y * __ldg(Wae + 9) +
                x0.z * __ldg(Wae + 10) + x0.w * __ldg(Wae + 11) +
                x1.x * __ldg(Wae + 12) + x1.y * __ldg(Wae + 13) +
                x1.z * __ldg(Wae + 14) + x1.w * __ldg(Wae + 15);

    float2 as = g_asrc[s];
    float2 ad = g_adst[d];
    float e0 = as.x + ad.x + ae0;
    float e1 = as.y + ad.y + ae1;
    e0 = (e0 >= 0.f) ? e0 : NEG_SLOPE * e0;
    e1 = (e1 >= 0.f) ? e1 : NEG_SLOPE * e1;
    g_ep[pos] = make_float2(__expf(e0), __expf(e1));
}

// ---------------- wmma GEMM, B full-K resident, cp.async.cg pipeline ---------
// C[*,128] = A[M,K] @ B[128,K]^T
// mode 0: Ch = half(acc + bias)   mode 1: Cf = relu(acc+bias) + h2f(add)
#define LDA 40
#define LDC 132
#define A_BUF_BYTES (128 * LDA * 2)    // 10240
#define B_OFF (2 * A_BUF_BYTES)        // 20480
#define DYN_SMEM (B_OFF + 128 * (256 + 8) * 2)   // 88064 (K=256 worst case)

__global__ void __launch_bounds__(256)
gemm_h_kernel(const __half* __restrict__ A,
              const __half* __restrict__ B0, const __half* __restrict__ B1,
              const float* __restrict__ bias0, const float* __restrict__ bias1,
              const __half* __restrict__ add,
              float* __restrict__ Cf,
              __half* __restrict__ C0h, __half* __restrict__ C1h,
              int M, int K, int mode) {
    extern __shared__ char dynsm[];
    __half* Asb[2] = {(__half*)dynsm, (__half*)(dynsm + A_BUF_BYTES)};
    __half* Bs = (__half*)(dynsm + B_OFF);
    float*  Cs = (float*)(dynsm + B_OFF);    // reused after mainloop
    const int LDB = K + 8;

    const __half* B    = (blockIdx.x == 0) ? B0 : B1;
    const float*  bias = (blockIdx.x == 0) ? bias0 : bias1;
    __half*       Ch   = (blockIdx.x == 0) ? C0h : C1h;

    int bm = blockIdx.y * 128;
    int t  = threadIdx.x;
    int w  = t >> 5;
    int wm = w & 3;
    int wn = w >> 2;

    int lr = t >> 1;
    int lh = (t & 1) * 16;
    int arow = bm + lr;
    bool ap_ok = (arow < M);
    const __half* a_base = A + (size_t)(ap_ok ? arow : (M - 1)) * K + lh;

    // ---- prologue: B (full K) + A chunk 0, one group ----
    {
        int cpr = K >> 3;               // 16B chunks per B row
        for (int idx = t; idx < 128 * cpr; idx += 256) {
            int row = idx / cpr;
            int ch = (idx % cpr) * 8;
            cp16cg(&Bs[row * LDB + ch], B + (size_t)row * K + ch, true);
        }
        cp16cg(&Asb[0][lr * LDA + lh], a_base, ap_ok);
        cp16cg(&Asb[0][lr * LDA + lh + 8], a_base + 8, ap_ok);
        cp_commit();
    }

    wmma::fragment<wmma::accumulator, 16, 16, 16, float> cf[2][4];
#pragma unroll
    for (int i = 0; i < 2; i++)
#pragma unroll
        for (int j = 0; j < 4; j++) wmma::fill_fragment(cf[i][j], 0.0f);

    const int nIter = K >> 5;
    for (int it = 0; it < nIter; it++) {
        int buf = it & 1;
        if (it + 1 < nIter) {
            int kt = (it + 1) << 5;
            cp16cg(&Asb[buf ^ 1][lr * LDA + lh], a_base + kt, ap_ok);
            cp16cg(&Asb[buf ^ 1][lr * LDA + lh + 8], a_base + kt + 8, ap_ok);
            cp_commit();
            cp_wait<1>();
        } else {
            cp_wait<0>();
        }
        __syncthreads();

        __half* As = Asb[buf];
        int kb = it << 5;
#pragma unroll
        for (int ks = 0; ks < 32; ks += 16) {
            wmma::fragment<wmma::matrix_a, 16, 16, 16, __half, wmma::row_major> af[2];
            wmma::fragment<wmma::matrix_b, 16, 16, 16, __half, wmma::col_major> bf[4];
#pragma unroll
            for (int i = 0; i < 2; i++)
                wmma::load_matrix_sync(af[i], &As[(wm * 32 + i * 16) * LDA + ks], LDA);
#pragma unroll
            for (int j = 0; j < 4; j++)
                wmma::load_matrix_sync(bf[j], &Bs[(wn * 64 + j * 16) * LDB + kb + ks], LDB);
#pragma unroll
            for (int i = 0; i < 2; i++)
#pragma unroll
                for (int j = 0; j < 4; j++)
                    wmma::mma_sync(cf[i][j], af[i], bf[j], cf[i][j]);
        }
        __syncthreads();
    }

    // stage C through smem (overlaps B region — mainloop done)
#pragma unroll
    for (int i = 0; i < 2; i++)
#pragma unroll
        for (int j = 0; j < 4; j++)
            wmma::store_matrix_sync(&Cs[(wm * 32 + i * 16) * LDC + wn * 64 + j * 16],
                                    cf[i][j], LDC, wmma::mem_row_major);
    __syncthreads();

    {
        int r = t >> 1;
        int cb = (t & 1) * 64;
        int row = bm + r;
        if (row < M) {
#pragma unroll
            for (int j = 0; j < 64; j += 4) {
                float4 v = *(float4*)&Cs[r * LDC + cb + j];
                if (bias) {
                    float4 b = *(const float4*)(bias + cb + j);
                    v.x += b.x; v.y += b.y; v.z += b.z; v.w += b.w;
                }
                if (mode == 1) {
                    uint2 ru = *(const uint2*)(add + (size_t)row * HF + cb + j);
                    __half2* rh = (__half2*)&ru;
                    float2 r0 = __half22float2(rh[0]);
                    float2 r1 = __half22float2(rh[1]);
                    v.x = fmaxf(v.x, 0.f) + r0.x;
                    v.y = fmaxf(v.y, 0.f) + r0.y;
                    v.z = fmaxf(v.z, 0.f) + r1.x;
                    v.w = fmaxf(v.w, 0.f) + r1.y;
                    *(float4*)(Cf + (size_t)row * HF + cb + j) = v;
                } else {
                    __half2 p[2] = {__floats2half2_rn(v.x, v.y),
                                    __floats2half2_rn(v.z, v.w)};
                    *(uint2*)(Ch + (size_t)row * HF + cb + j) = *(uint2*)p;
                }
            }
        }
    }
}

// ---------------- pull aggregation: single pass, warp per dst node -----------
__global__ void agg_kernel() {
    int warp = (blockIdx.x * blockDim.x + threadIdx.x) >> 5;
    if (warp >= NN) return;
    int lane = threadIdx.x & 31;

    int row = g_off[warp];
    int end = g_off[warp + 1];

    const int elem = lane * 4;
    const bool h0 = (lane < 16);
    float z = 0.f;
    float a0 = 0.f, a1 = 0.f, a2 = 0.f, a3 = 0.f;

    int j = row;
    for (; j + 2 <= end; j += 2) {
        float2 e0 = g_ep[j];
        float2 e1 = g_ep[j + 1];
        int s0 = g_psrc[j];
        int s1 = g_psrc[j + 1];
        float c0 = h0 ? e0.x : e0.y;
        float c1 = h0 ? e1.x : e1.y;
        z += c0 + c1;
        const __half2* p0 = (const __half2*)(g_hsrc_h + (size_t)s0 * HF + elem);
        const __half2* p1 = (const __half2*)(g_hsrc_h + (size_t)s1 * HF + elem);
        __half2 u0 = p0[0], u1 = p0[1];
        __half2 v0 = p1[0], v1 = p1[1];
        float2 fu0 = __half22float2(u0), fu1 = __half22float2(u1);
        float2 fv0 = __half22float2(v0), fv1 = __half22float2(v1);
        a0 = fmaf(fu0.x, c0, a0); a1 = fmaf(fu0.y, c0, a1);
        a2 = fmaf(fu1.x, c0, a2); a3 = fmaf(fu1.y, c0, a3);
        a0 = fmaf(fv0.x, c1, a0); a1 = fmaf(fv0.y, c1, a1);
        a2 = fmaf(fv1.x, c1, a2); a3 = fmaf(fv1.y, c1, a3);
    }
    if (j < end) {
        float2 e0 = g_ep[j];
        int s0 = g_psrc[j];
        float c0 = h0 ? e0.x : e0.y;
        z += c0;
        const __half2* p0 = (const __half2*)(g_hsrc_h + (size_t)s0 * HF + elem);
        __half2 u0 = p0[0], u1 = p0[1];
        float2 fu0 = __half22float2(u0), fu1 = __half22float2(u1);
        a0 = fmaf(fu0.x, c0, a0); a1 = fmaf(fu0.y, c0, a1);
        a2 = fmaf(fu1.x, c0, a2); a3 = fmaf(fu1.y, c0, a3);
    }

    float invz = (end > row) ? __fdividef(1.f, z) : 0.f;
    __half2 hh[2] = {__floats2half2_rn(a0 * invz, a1 * invz),
                     __floats2half2_rn(a2 * invz, a3 * invz)};
    *(uint2*)(g_rst_h + (size_t)warp * HF + elem) = *(uint2*)hh;
}

// ---------------- launch -----------------------------------------------------
extern "C" void kernel_launch(void* const* d_in, const int* in_sizes, int n_in,
                              void* d_out, int out_size) {
    const float* feat_src    = (const float*)d_in[0];
    const float* feat_edge   = (const float*)d_in[1];
    const int*   edge_src    = (const int*)d_in[2];
    const int*   edge_dst    = (const int*)d_in[3];
    const float* W_src       = (const float*)d_in[4];
    const float* W_dst       = (const float*)d_in[5];
    const float* b_dst       = (const float*)d_in[6];
    const float* W_attn_src  = (const float*)d_in[7];
    const float* W_attn_dst  = (const float*)d_in[8];
    const float* W_attn_edge = (const float*)d_in[9];
    const float* W_ngnn      = (const float*)d_in[10];
    const float* b_ngnn      = (const float*)d_in[11];
    float* out = (float*)d_out;

    __half* feat_h;  cudaGetSymbolAddress((void**)&feat_h,  g_feat_h);
    __half* wsrc_h;  cudaGetSymbolAddress((void**)&wsrc_h,  g_wsrc_h);
    __half* wdst_h;  cudaGetSymbolAddress((void**)&wdst_h,  g_wdst_h);
    __half* wngnn_h; cudaGetSymbolAddress((void**)&wngnn_h, g_wngnn_h);
    __half* hsrc_h;  cudaGetSymbolAddress((void**)&hsrc_h,  g_hsrc_h);
    __half* hdst_h;  cudaGetSymbolAddress((void**)&hdst_h,  g_hdst_h);
    __half* rst_h;   cudaGetSymbolAddress((void**)&rst_h,   g_rst_h);

    static bool attr_set = false;
    if (!attr_set) {
        cudaFuncSetAttribute(gemm_h_kernel,
                             cudaFuncAttributeMaxDynamicSharedMemorySize,
                             DYN_SMEM);
        attr_set = true;
    }

    // 0: weights + histogram + feat conversion + attention logits
    phase1_kernel<<<WCONV_BLOCKS + HIST_BLOCKS + 1024, 256>>>(
        feat_src, W_attn_src, W_attn_dst, W_src, W_dst, W_ngnn, edge_dst);

    // 1-2: CSR scan (scan1 self-cleans g_cnt)
    scan1_kernel<<<NB, 1024>>>();
    scan2_kernel<<<1, 128>>>();

    // 3: node GEMMs (h_src & h_dst fp16) — profiled slot
    gemm_h_kernel<<<dim3(2, (NN + 127) / 128), 256, DYN_SMEM>>>(
        feat_h, wsrc_h, wdst_h, nullptr, b_dst, nullptr,
        nullptr, hsrc_h, hdst_h, NN, DD, 0);

    // 4: finish CSR offsets
    scan3_kernel<<<(NN + 255) / 256, 256>>>();

    // 5: fused scatter + edge logits + exp
    scatter_edge_kernel<<<(EE + 255) / 256, 256>>>(edge_src, edge_dst,
                                                   feat_edge, W_attn_edge);

    // 6: pull aggregation (single-pass softmax + weighted sum)
    agg_kernel<<<(NN * 32 + 255) / 256, 256>>>();

    // 7: NGNN GEMM + ReLU + bias + fp16 residual -> fp32 out
    gemm_h_kernel<<<dim3(1, (NN + 127) / 128), 256, DYN_SMEM>>>(
        rst_h, wngnn_h, wngnn_h, b_ngnn, b_ngnn, hdst_h,
        out, nullptr, nullptr, NN, HF, 1);
}

// round 13
// speedup vs baseline: 1.1608x; 1.0512x over previous
#include <cuda_runtime.h>
#include <cuda_fp16.h>
#include <mma.h>
#include <math.h>
#include <stdint.h>

using namespace nvcuda;

#define NN 100000
#define EE 1600000
#define DD 256
#define DE 8
#define HF 128
#define NEG_SLOPE 0.2f
#define NB ((NN + 1023) / 1024)
#define WCONV_BLOCKS 40
#define HIST_BLOCKS ((EE + 255) / 256)

// ---------------- scratch (device globals) ----------------------------------
__device__ __half  g_feat_h[(size_t)NN * DD];
__device__ __half  g_wsrc_h[HF * DD];
__device__ __half  g_wdst_h[HF * DD];
__device__ __half  g_wngnn_h[HF * HF];
__device__ __half  g_hsrc_h[(size_t)NN * HF];
__device__ __half  g_hdst_h[(size_t)NN * HF];
__device__ __half  g_rst_h[(size_t)NN * HF];
__device__ float2  g_asrc[NN];
__device__ float2  g_adst[NN];
__device__ float2  g_ep  [EE];
__device__ int     g_cnt [NN];
__device__ int     g_off [NN + 1];
__device__ int     g_cur [NN];
__device__ int     g_psrc[EE];
__device__ int     g_tmp [NN];
__device__ int     g_bsum[128];

// ---------------- cp.async helpers (.cg = bypass L1) --------------------------
static __device__ __forceinline__ void cp16cg(__half* s, const __half* g, bool pred) {
    unsigned sa = (unsigned)__cvta_generic_to_shared(s);
    int sz = pred ? 16 : 0;
    asm volatile("cp.async.cg.shared.global [%0], [%1], 16, %2;"
                 :: "r"(sa), "l"(g), "r"(sz));
}
static __device__ __forceinline__ void cp_commit() {
    asm volatile("cp.async.commit_group;" ::: "memory");
}
template <int N>
static __device__ __forceinline__ void cp_wait() {
    asm volatile("cp.async.wait_group %0;" :: "n"(N) : "memory");
}

// ---------------- phase 1: wconv + hist + feat f2h + attn logits -------------
static __device__ __forceinline__ float dot8(float4 x0, float4 x1,
                                             float4 w0, float4 w1) {
    float s = x0.x * w0.x;
    s = fmaf(x0.y, w0.y, s); s = fmaf(x0.z, w0.z, s); s = fmaf(x0.w, w0.w, s);
    s = fmaf(x1.x, w1.x, s); s = fmaf(x1.y, w1.y, s);
    s = fmaf(x1.z, w1.z, s); s = fmaf(x1.w, w1.w, s);
    return s;
}

__global__ void phase1_kernel(const float* __restrict__ feat,
                              const float* __restrict__ Was,
                              const float* __restrict__ Wad,
                              const float* __restrict__ Wsrc,
                              const float* __restrict__ Wdst,
                              const float* __restrict__ Wngnn,
                              const int* __restrict__ ed) {
    if (blockIdx.x < WCONV_BLOCKS) {
        int i = blockIdx.x * blockDim.x + threadIdx.x;
        const int n1 = HF * DD / 8, n2 = 2 * n1, n3 = n2 + HF * HF / 8;
        const float* src;
        __half* dst;
        int k;
        if (i < n1)      { src = Wsrc;  dst = g_wsrc_h;  k = i; }
        else if (i < n2) { src = Wdst;  dst = g_wdst_h;  k = i - n1; }
        else if (i < n3) { src = Wngnn; dst = g_wngnn_h; k = i - n2; }
        else return;
        const float4* s = (const float4*)(src + (size_t)k * 8);
        float4 a = s[0], b = s[1];
        __half2 h[4] = {__floats2half2_rn(a.x, a.y), __floats2half2_rn(a.z, a.w),
                        __floats2half2_rn(b.x, b.y), __floats2half2_rn(b.z, b.w)};
        *(uint4*)(dst + (size_t)k * 8) = *(uint4*)h;
        return;
    }
    if (blockIdx.x < WCONV_BLOCKS + HIST_BLOCKS) {
        int i = (blockIdx.x - WCONV_BLOCKS) * blockDim.x + threadIdx.x;
        if (i < EE) atomicAdd(&g_cnt[ed[i]], 1);
        return;
    }

    int lane = threadIdx.x & 31;
    int base = WCONV_BLOCKS + HIST_BLOCKS;
    int warp = ((blockIdx.x - base) * blockDim.x + threadIdx.x) >> 5;
    int nwarps = ((gridDim.x - base) * blockDim.x) >> 5;
    int cb = lane * 8;

    float4 ws0a = *(const float4*)(Was + cb);
    float4 ws0b = *(const float4*)(Was + cb + 4);
    float4 ws1a = *(const float4*)(Was + DD + cb);
    float4 ws1b = *(const float4*)(Was + DD + cb + 4);
    float4 wd0a = *(const float4*)(Wad + cb);
    float4 wd0b = *(const float4*)(Wad + cb + 4);
    float4 wd1a = *(const float4*)(Wad + DD + cb);
    float4 wd1b = *(const float4*)(Wad + DD + cb + 4);

    for (int n = warp; n < NN; n += nwarps) {
        const float* fp = feat + (size_t)n * DD + cb;
        float4 x0 = *(const float4*)fp;
        float4 x1 = *(const float4*)(fp + 4);

        __half2 h[4] = {__floats2half2_rn(x0.x, x0.y),
                        __floats2half2_rn(x0.z, x0.w),
                        __floats2half2_rn(x1.x, x1.y),
                        __floats2half2_rn(x1.z, x1.w)};
        *(uint4*)(g_feat_h + (size_t)n * DD + cb) = *(uint4*)h;

        float s0 = dot8(x0, x1, ws0a, ws0b);
        float s1 = dot8(x0, x1, ws1a, ws1b);
        float d0 = dot8(x0, x1, wd0a, wd0b);
        float d1 = dot8(x0, x1, wd1a, wd1b);
#pragma unroll
        for (int off = 16; off > 0; off >>= 1) {
            s0 += __shfl_xor_sync(0xffffffff, s0, off);
            s1 += __shfl_xor_sync(0xffffffff, s1, off);
            d0 += __shfl_xor_sync(0xffffffff, d0, off);
            d1 += __shfl_xor_sync(0xffffffff, d1, off);
        }
        if (lane == 0) {
            g_asrc[n] = make_float2(s0, s1);
            g_adst[n] = make_float2(d0, d1);
        }
    }
}

// ---------------- CSR scan ----------------------------------------------------
__global__ void scan1_kernel() {
    __shared__ int sh[1024];
    int t = threadIdx.x;
    int gi = blockIdx.x * 1024 + t;
    int v = (gi < NN) ? g_cnt[gi] : 0;
    if (gi < NN) g_cnt[gi] = 0;
    sh[t] = v;
    __syncthreads();
#pragma unroll
    for (int off = 1; off < 1024; off <<= 1) {
        int add = (t >= off) ? sh[t - off] : 0;
        __syncthreads();
        sh[t] += add;
        __syncthreads();
    }
    if (gi < NN) g_tmp[gi] = sh[t] - v;
    if (t == 1023) g_bsum[blockIdx.x] = sh[1023];
}

__global__ void scan2_kernel() {
    __shared__ int sh[128];
    int t = threadIdx.x;
    int v = (t < NB) ? g_bsum[t] : 0;
    sh[t] = v;
    __syncthreads();
#pragma unroll
    for (int off = 1; off < 128; off <<= 1) {
        int add = (t >= off) ? sh[t - off] : 0;
        __syncthreads();
        sh[t] += add;
        __syncthreads();
    }
    if (t < NB) g_bsum[t] = sh[t] - v;
}

__global__ void scan3_kernel() {
    int i = blockIdx.x * blockDim.x + threadIdx.x;
    if (i < NN) {
        int o = g_tmp[i] + g_bsum[i >> 10];
        g_off[i] = o;
        g_cur[i] = o;
    }
    if (i == 0) g_off[NN] = EE;
}

// ---------------- fused: CSR scatter + edge logit + leaky + exp --------------
__global__ void scatter_edge_kernel(const int* __restrict__ es,
                                    const int* __restrict__ ed,
                                    const float* __restrict__ fe,
                                    const float* __restrict__ Wae) {
    int i = blockIdx.x * blockDim.x + threadIdx.x;
    if (i >= EE) return;

    int s = es[i], d = ed[i];
    int pos = atomicAdd(&g_cur[d], 1);
    g_psrc[pos] = s;

    float4 x0 = *(const float4*)(fe + (size_t)i * DE);
    float4 x1 = *(const float4*)(fe + (size_t)i * DE + 4);

    float ae0 = x0.x * __ldg(Wae + 0) + x0.y * __ldg(Wae + 1) +
                x0.z * __ldg(Wae + 2) + x0.w * __ldg(Wae + 3) +
                x1.x * __ldg(Wae + 4) + x1.y * __ldg(Wae + 5) +
                x1.z * __ldg(Wae + 6) + x1.w * __ldg(Wae + 7);
    float ae1 = x0.x * __ldg(Wae + 8)  + x0.y * __ldg(Wae + 9) +
                x0.z * __ldg(Wae + 10) + x0.w * __ldg(Wae + 11) +
                x1.x * __ldg(Wae + 12) + x1.y * __ldg(Wae + 13) +
                x1.z * __ldg(Wae + 14) + x1.w * __ldg(Wae + 15);

    float2 as = g_asrc[s];
    float2 ad = g_adst[d];
    float e0 = as.x + ad.x + ae0;
    float e1 = as.y + ad.y + ae1;
    e0 = (e0 >= 0.f) ? e0 : NEG_SLOPE * e0;
    e1 = (e1 >= 0.f) ? e1 : NEG_SLOPE * e1;
    g_ep[pos] = make_float2(__expf(e0), __expf(e1));
}

// ---------------- wmma GEMM: 3-stage A pipeline, B full-K resident -----------
// C[*,128] = A[M,K] @ B[128,K]^T
// mode 0: Ch = half(acc + bias)   mode 1: Cf = relu(acc+bias) + h2f(add)
#define LDA 40
#define LDC 132
#define A_BUF_BYTES (128 * LDA * 2)        // 10240
#define B_OFF (3 * A_BUF_BYTES)            // 30720
// B/Cs overlay: max(128*(K+8)*2, 64*LDC*4)
template <int K>
__global__ void __launch_bounds__(256)
gemm_h_kernel(const __half* __restrict__ A,
              const __half* __restrict__ B0, const __half* __restrict__ B1,
              const float* __restrict__ bias0, const float* __restrict__ bias1,
              const __half* __restrict__ add,
              float* __restrict__ Cf,
              __half* __restrict__ C0h, __half* __restrict__ C1h,
              int M, int mode) {
    extern __shared__ char dynsm[];
    __half* Asb[3] = {(__half*)dynsm, (__half*)(dynsm + A_BUF_BYTES),
                      (__half*)(dynsm + 2 * A_BUF_BYTES)};
    __half* Bs = (__half*)(dynsm + B_OFF);
    float*  Cs = (float*)(dynsm + B_OFF);       // overlays B after mainloop
    const int LDB = K + 8;

    const __half* B    = (blockIdx.x == 0) ? B0 : B1;
    const float*  bias = (blockIdx.x == 0) ? bias0 : bias1;
    __half*       Ch   = (blockIdx.x == 0) ? C0h : C1h;

    int bm = blockIdx.y * 128;
    int t  = threadIdx.x;
    int w  = t >> 5;
    int wm = w & 3;
    int wn = w >> 2;

    int lr = t >> 1;
    int lh = (t & 1) * 16;
    int arow = bm + lr;
    bool ap_ok = (arow < M);
    const __half* a_base = A + (size_t)(ap_ok ? arow : (M - 1)) * K + lh;

    constexpr int nIter = K >> 5;

    // prologue: group0 = B (full K) + A chunk0; group1 = A chunk1
    {
        constexpr int cpr = K >> 3;
        for (int idx = t; idx < 128 * cpr; idx += 256) {
            int row = idx / cpr;
            int ch = (idx % cpr) * 8;
            cp16cg(&Bs[row * LDB + ch], B + (size_t)row * K + ch, true);
        }
        cp16cg(&Asb[0][lr * LDA + lh], a_base, ap_ok);
        cp16cg(&Asb[0][lr * LDA + lh + 8], a_base + 8, ap_ok);
        cp_commit();
        if (nIter > 1) {
            cp16cg(&Asb[1][lr * LDA + lh], a_base + 32, ap_ok);
            cp16cg(&Asb[1][lr * LDA + lh + 8], a_base + 40, ap_ok);
        }
        cp_commit();
    }

    wmma::fragment<wmma::accumulator, 16, 16, 16, float> cf[2][4];
#pragma unroll
    for (int i = 0; i < 2; i++)
#pragma unroll
        for (int j = 0; j < 4; j++) wmma::fill_fragment(cf[i][j], 0.0f);

#pragma unroll
    for (int it = 0; it < nIter; it++) {
        cp_wait<1>();
        __syncthreads();

        __half* As = Asb[it % 3];
        int kb = it << 5;
#pragma unroll
        for (int ks = 0; ks < 32; ks += 16) {
            wmma::fragment<wmma::matrix_a, 16, 16, 16, __half, wmma::row_major> af[2];
            wmma::fragment<wmma::matrix_b, 16, 16, 16, __half, wmma::col_major> bf[4];
#pragma unroll
            for (int i = 0; i < 2; i++)
                wmma::load_matrix_sync(af[i], &As[(wm * 32 + i * 16) * LDA + ks], LDA);
#pragma unroll
            for (int j = 0; j < 4; j++)
                wmma::load_matrix_sync(bf[j], &Bs[(wn * 64 + j * 16) * LDB + kb + ks], LDB);
#pragma unroll
            for (int i = 0; i < 2; i++)
#pragma unroll
                for (int j = 0; j < 4; j++)
                    wmma::mma_sync(cf[i][j], af[i], bf[j], cf[i][j]);
        }

        if (it + 2 < nIter) {
            int kt = (it + 2) << 5;
            __half* Ap = Asb[(it + 2) % 3];
            cp16cg(&Ap[lr * LDA + lh], a_base + kt, ap_ok);
            cp16cg(&Ap[lr * LDA + lh + 8], a_base + kt + 8, ap_ok);
        }
        cp_commit();   // keep group count in lockstep even when empty
    }
    __syncthreads();   // B reads done before Cs overlay

    // epilogue: two 64-row half-passes through Cs
#pragma unroll
    for (int half = 0; half < 2; half++) {
        if ((wm >> 1) == half) {
            int wml = wm & 1;   // 0..1 within half
#pragma unroll
            for (int i = 0; i < 2; i++)
#pragma unroll
                for (int j = 0; j < 4; j++)
                    wmma::store_matrix_sync(
                        &Cs[(wml * 32 + i * 16) * LDC + wn * 64 + j * 16],
                        cf[i][j], LDC, wmma::mem_row_major);
        }
        __syncthreads();

        {
            int r = t >> 2;                 // 0..63
            int cb = (t & 3) * 32;          // 32 cols per thread
            int row = bm + half * 64 + r;
            if (row < M) {
#pragma unroll
                for (int j = 0; j < 32; j += 4) {
                    float4 v = *(float4*)&Cs[r * LDC + cb + j];
                    if (bias) {
                        float4 b = *(const float4*)(bias + cb + j);
                        v.x += b.x; v.y += b.y; v.z += b.z; v.w += b.w;
                    }
                    if (mode == 1) {
                        uint2 ru = *(const uint2*)(add + (size_t)row * HF + cb + j);
                        __half2* rh = (__half2*)&ru;
                        float2 r0 = __half22float2(rh[0]);
                        float2 r1 = __half22float2(rh[1]);
                        v.x = fmaxf(v.x, 0.f) + r0.x;
                        v.y = fmaxf(v.y, 0.f) + r0.y;
                        v.z = fmaxf(v.z, 0.f) + r1.x;
                        v.w = fmaxf(v.w, 0.f) + r1.y;
                        *(float4*)(Cf + (size_t)row * HF + cb + j) = v;
                    } else {
                        __half2 p[2] = {__floats2half2_rn(v.x, v.y),
                                        __floats2half2_rn(v.z, v.w)};
                        *(uint2*)(Ch + (size_t)row * HF + cb + j) = *(uint2*)p;
                    }
                }
            }
        }
        __syncthreads();
    }
}

// ---------------- pull aggregation: single pass, warp per dst node -----------
__global__ void agg_kernel() {
    int warp = (blockIdx.x * blockDim.x + threadIdx.x) >> 5;
    if (warp >= NN) return;
    int lane = threadIdx.x & 31;

    int row = g_off[warp];
    int end = g_off[warp + 1];

    const int elem = lane * 4;
    const bool h0 = (lane < 16);
    float z = 0.f;
    float a0 = 0.f, a1 = 0.f, a2 = 0.f, a3 = 0.f;

    int j = row;
    for (; j + 2 <= end; j += 2) {
        float2 e0 = g_ep[j];
        float2 e1 = g_ep[j + 1];
        int s0 = g_psrc[j];
        int s1 = g_psrc[j + 1];
        float c0 = h0 ? e0.x : e0.y;
        float c1 = h0 ? e1.x : e1.y;
        z += c0 + c1;
        const __half2* p0 = (const __half2*)(g_hsrc_h + (size_t)s0 * HF + elem);
        const __half2* p1 = (const __half2*)(g_hsrc_h + (size_t)s1 * HF + elem);
        __half2 u0 = p0[0], u1 = p0[1];
        __half2 v0 = p1[0], v1 = p1[1];
        float2 fu0 = __half22float2(u0), fu1 = __half22float2(u1);
        float2 fv0 = __half22float2(v0), fv1 = __half22float2(v1);
        a0 = fmaf(fu0.x, c0, a0); a1 = fmaf(fu0.y, c0, a1);
        a2 = fmaf(fu1.x, c0, a2); a3 = fmaf(fu1.y, c0, a3);
        a0 = fmaf(fv0.x, c1, a0); a1 = fmaf(fv0.y, c1, a1);
        a2 = fmaf(fv1.x, c1, a2); a3 = fmaf(fv1.y, c1, a3);
    }
    if (j < end) {
        float2 e0 = g_ep[j];
        int s0 = g_psrc[j];
        float c0 = h0 ? e0.x : e0.y;
        z += c0;
        const __half2* p0 = (const __half2*)(g_hsrc_h + (size_t)s0 * HF + elem);
        __half2 u0 = p0[0], u1 = p0[1];
        float2 fu0 = __half22float2(u0), fu1 = __half22float2(u1);
        a0 = fmaf(fu0.x, c0, a0); a1 = fmaf(fu0.y, c0, a1);
        a2 = fmaf(fu1.x, c0, a2); a3 = fmaf(fu1.y, c0, a3);
    }

    float invz = (end > row) ? __fdividef(1.f, z) : 0.f;
    __half2 hh[2] = {__floats2half2_rn(a0 * invz, a1 * invz),
                     __floats2half2_rn(a2 * invz, a3 * invz)};
    *(uint2*)(g_rst_h + (size_t)warp * HF + elem) = *(uint2*)hh;
}

// ---------------- launch -----------------------------------------------------
extern "C" void kernel_launch(void* const* d_in, const int* in_sizes, int n_in,
                              void* d_out, int out_size) {
    const float* feat_src    = (const float*)d_in[0];
    const float* feat_edge   = (const float*)d_in[1];
    const int*   edge_src    = (const int*)d_in[2];
    const int*   edge_dst    = (const int*)d_in[3];
    const float* W_src       = (const float*)d_in[4];
    const float* W_dst       = (const float*)d_in[5];
    const float* b_dst       = (const float*)d_in[6];
    const float* W_attn_src  = (const float*)d_in[7];
    const float* W_attn_dst  = (const float*)d_in[8];
    const float* W_attn_edge = (const float*)d_in[9];
    const float* W_ngnn      = (const float*)d_in[10];
    const float* b_ngnn      = (const float*)d_in[11];
    float* out = (float*)d_out;

    __half* feat_h;  cudaGetSymbolAddress((void**)&feat_h,  g_feat_h);
    __half* wsrc_h;  cudaGetSymbolAddress((void**)&wsrc_h,  g_wsrc_h);
    __half* wdst_h;  cudaGetSymbolAddress((void**)&wdst_h,  g_wdst_h);
    __half* wngnn_h; cudaGetSymbolAddress((void**)&wngnn_h, g_wngnn_h);
    __half* hsrc_h;  cudaGetSymbolAddress((void**)&hsrc_h,  g_hsrc_h);
    __half* hdst_h;  cudaGetSymbolAddress((void**)&hdst_h,  g_hdst_h);
    __half* rst_h;   cudaGetSymbolAddress((void**)&rst_h,   g_rst_h);

    const int smem256 = B_OFF + 128 * (256 + 8) * 2;   // 98304
    const int smem128 = B_OFF + 128 * (128 + 8) * 2;   // 65536 (>= Cs half 33792+B_OFF)

    static bool attr_set = false;
    if (!attr_set) {
        cudaFuncSetAttribute(gemm_h_kernel<256>,
                             cudaFuncAttributeMaxDynamicSharedMemorySize, smem256);
        cudaFuncSetAttribute(gemm_h_kernel<128>,
                             cudaFuncAttributeMaxDynamicSharedMemorySize, smem128);
        attr_set = true;
    }

    // 0: weights + histogram + feat conversion + attention logits
    phase1_kernel<<<WCONV_BLOCKS + HIST_BLOCKS + 1024, 256>>>(
        feat_src, W_attn_src, W_attn_dst, W_src, W_dst, W_ngnn, edge_dst);

    // 1-2: CSR scan (scan1 self-cleans g_cnt)
    scan1_kernel<<<NB, 1024>>>();
    scan2_kernel<<<1, 128>>>();

    // 3: node GEMMs (h_src & h_dst fp16) — profiled slot
    gemm_h_kernel<256><<<dim3(2, (NN + 127) / 128), 256, smem256>>>(
        feat_h, wsrc_h, wdst_h, nullptr, b_dst, nullptr,
        nullptr, hsrc_h, hdst_h, NN, 0);

    // 4: finish CSR offsets
    scan3_kernel<<<(NN + 255) / 256, 256>>>();

    // 5: fused scatter + edge logits + exp
    scatter_edge_kernel<<<(EE + 255) / 256, 256>>>(edge_src, edge_dst,
                                                   feat_edge, W_attn_edge);

    // 6: pull aggregation (single-pass softmax + weighted sum)
    agg_kernel<<<(NN * 32 + 255) / 256, 256>>>();

    // 7: NGNN GEMM + ReLU + bias + fp16 residual -> fp32 out
    gemm_h_kernel<128><<<dim3(1, (NN + 127) / 128), 256, smem128>>>(
        rst_h, wngnn_h, wngnn_h, b_ngnn, b_ngnn, hdst_h,
        out, nullptr, nullptr, NN, 1);
}

// round 14
// speedup vs baseline: 1.2048x; 1.0379x over previous
#include <cuda_runtime.h>
#include <cuda_fp16.h>
#include <mma.h>
#include <math.h>
#include <stdint.h>

using namespace nvcuda;

#define NN 100000
#define EE 1600000
#define DD 256
#define DE 8
#define HF 128
#define NEG_SLOPE 0.2f
#define NB ((NN + 1023) / 1024)
#define WCONV_BLOCKS 40
#define HIST_BLOCKS ((EE + 255) / 256)

// ---------------- scratch (device globals) ----------------------------------
__device__ __half  g_feat_h[(size_t)NN * DD];
__device__ __half  g_wsrc_h[HF * DD];
__device__ __half  g_wdst_h[HF * DD];
__device__ __half  g_wngnn_h[HF * HF];
__device__ __half  g_hsrc_h[(size_t)NN * HF];
__device__ __half  g_hdst_h[(size_t)NN * HF];
__device__ __half  g_rst_h[(size_t)NN * HF];
__device__ float2  g_asrc[NN];
__device__ float2  g_adst[NN];
__device__ float2  g_ep  [EE];
__device__ int     g_cnt [NN];
__device__ int     g_off [NN + 1];
__device__ int     g_cur [NN];
__device__ int     g_psrc[EE];
__device__ int     g_tmp [NN];
__device__ int     g_bsum[128];

// ---------------- cp.async helpers (.cg = bypass L1) --------------------------
static __device__ __forceinline__ void cp16cg(__half* s, const __half* g, bool pred) {
    unsigned sa = (unsigned)__cvta_generic_to_shared(s);
    int sz = pred ? 16 : 0;
    asm volatile("cp.async.cg.shared.global [%0], [%1], 16, %2;"
                 :: "r"(sa), "l"(g), "r"(sz));
}
static __device__ __forceinline__ void cp_commit() {
    asm volatile("cp.async.commit_group;" ::: "memory");
}
template <int N>
static __device__ __forceinline__ void cp_wait() {
    asm volatile("cp.async.wait_group %0;" :: "n"(N) : "memory");
}

// ---------------- phase 1: wconv + hist + feat f2h + attn logits -------------
static __device__ __forceinline__ float dot8(float4 x0, float4 x1,
                                             float4 w0, float4 w1) {
    float s = x0.x * w0.x;
    s = fmaf(x0.y, w0.y, s); s = fmaf(x0.z, w0.z, s); s = fmaf(x0.w, w0.w, s);
    s = fmaf(x1.x, w1.x, s); s = fmaf(x1.y, w1.y, s);
    s = fmaf(x1.z, w1.z, s); s = fmaf(x1.w, w1.w, s);
    return s;
}

__global__ void phase1_kernel(const float* __restrict__ feat,
                              const float* __restrict__ Was,
                              const float* __restrict__ Wad,
                              const float* __restrict__ Wsrc,
                              const float* __restrict__ Wdst,
                              const float* __restrict__ Wngnn,
                              const int* __restrict__ ed) {
    if (blockIdx.x < WCONV_BLOCKS) {
        int i = blockIdx.x * blockDim.x + threadIdx.x;
        const int n1 = HF * DD / 8, n2 = 2 * n1, n3 = n2 + HF * HF / 8;
        const float* src;
        __half* dst;
        int k;
        if (i < n1)      { src = Wsrc;  dst = g_wsrc_h;  k = i; }
        else if (i < n2) { src = Wdst;  dst = g_wdst_h;  k = i - n1; }
        else if (i < n3) { src = Wngnn; dst = g_wngnn_h; k = i - n2; }
        else return;
        const float4* s = (const float4*)(src + (size_t)k * 8);
        float4 a = s[0], b = s[1];
        __half2 h[4] = {__floats2half2_rn(a.x, a.y), __floats2half2_rn(a.z, a.w),
                        __floats2half2_rn(b.x, b.y), __floats2half2_rn(b.z, b.w)};
        *(uint4*)(dst + (size_t)k * 8) = *(uint4*)h;
        return;
    }
    if (blockIdx.x < WCONV_BLOCKS + HIST_BLOCKS) {
        int i = (blockIdx.x - WCONV_BLOCKS) * blockDim.x + threadIdx.x;
        if (i < EE) atomicAdd(&g_cnt[ed[i]], 1);
        return;
    }

    int lane = threadIdx.x & 31;
    int base = WCONV_BLOCKS + HIST_BLOCKS;
    int warp = ((blockIdx.x - base) * blockDim.x + threadIdx.x) >> 5;
    int nwarps = ((gridDim.x - base) * blockDim.x) >> 5;
    int cb = lane * 8;

    float4 ws0a = *(const float4*)(Was + cb);
    float4 ws0b = *(const float4*)(Was + cb + 4);
    float4 ws1a = *(const float4*)(Was + DD + cb);
    float4 ws1b = *(const float4*)(Was + DD + cb + 4);
    float4 wd0a = *(const float4*)(Wad + cb);
    float4 wd0b = *(const float4*)(Wad + cb + 4);
    float4 wd1a = *(const float4*)(Wad + DD + cb);
    float4 wd1b = *(const float4*)(Wad + DD + cb + 4);

    // two nodes per iteration for MLP
    for (int n = warp * 2; n < NN; n += nwarps * 2) {
        int nA = n;
        int nB = n + 1;
        bool okB = (nB < NN);

        const float* fpA = feat + (size_t)nA * DD + cb;
        const float* fpB = feat + (size_t)(okB ? nB : nA) * DD + cb;
        float4 xa0 = *(const float4*)fpA;
        float4 xa1 = *(const float4*)(fpA + 4);
        float4 xb0 = *(const float4*)fpB;
        float4 xb1 = *(const float4*)(fpB + 4);

        __half2 ha[4] = {__floats2half2_rn(xa0.x, xa0.y),
                         __floats2half2_rn(xa0.z, xa0.w),
                         __floats2half2_rn(xa1.x, xa1.y),
                         __floats2half2_rn(xa1.z, xa1.w)};
        *(uint4*)(g_feat_h + (size_t)nA * DD + cb) = *(uint4*)ha;
        if (okB) {
            __half2 hb[4] = {__floats2half2_rn(xb0.x, xb0.y),
                             __floats2half2_rn(xb0.z, xb0.w),
                             __floats2half2_rn(xb1.x, xb1.y),
                             __floats2half2_rn(xb1.z, xb1.w)};
            *(uint4*)(g_feat_h + (size_t)nB * DD + cb) = *(uint4*)hb;
        }

        float as0 = dot8(xa0, xa1, ws0a, ws0b);
        float as1 = dot8(xa0, xa1, ws1a, ws1b);
        float ad0 = dot8(xa0, xa1, wd0a, wd0b);
        float ad1 = dot8(xa0, xa1, wd1a, wd1b);
        float bs0 = dot8(xb0, xb1, ws0a, ws0b);
        float bs1 = dot8(xb0, xb1, ws1a, ws1b);
        float bd0 = dot8(xb0, xb1, wd0a, wd0b);
        float bd1 = dot8(xb0, xb1, wd1a, wd1b);
#pragma unroll
        for (int off = 16; off > 0; off >>= 1) {
            as0 += __shfl_xor_sync(0xffffffff, as0, off);
            as1 += __shfl_xor_sync(0xffffffff, as1, off);
            ad0 += __shfl_xor_sync(0xffffffff, ad0, off);
            ad1 += __shfl_xor_sync(0xffffffff, ad1, off);
            bs0 += __shfl_xor_sync(0xffffffff, bs0, off);
            bs1 += __shfl_xor_sync(0xffffffff, bs1, off);
            bd0 += __shfl_xor_sync(0xffffffff, bd0, off);
            bd1 += __shfl_xor_sync(0xffffffff, bd1, off);
        }
        if (lane == 0) {
            g_asrc[nA] = make_float2(as0, as1);
            g_adst[nA] = make_float2(ad0, ad1);
            if (okB) {
                g_asrc[nB] = make_float2(bs0, bs1);
                g_adst[nB] = make_float2(bd0, bd1);
            }
        }
    }
}

// ---------------- CSR scan ----------------------------------------------------
__global__ void scan1_kernel() {
    __shared__ int sh[1024];
    int t = threadIdx.x;
    int gi = blockIdx.x * 1024 + t;
    int v = (gi < NN) ? g_cnt[gi] : 0;
    if (gi < NN) g_cnt[gi] = 0;
    sh[t] = v;
    __syncthreads();
#pragma unroll
    for (int off = 1; off < 1024; off <<= 1) {
        int add = (t >= off) ? sh[t - off] : 0;
        __syncthreads();
        sh[t] += add;
        __syncthreads();
    }
    if (gi < NN) g_tmp[gi] = sh[t] - v;
    if (t == 1023) g_bsum[blockIdx.x] = sh[1023];
}

__global__ void scan2_kernel() {
    __shared__ int sh[128];
    int t = threadIdx.x;
    int v = (t < NB) ? g_bsum[t] : 0;
    sh[t] = v;
    __syncthreads();
#pragma unroll
    for (int off = 1; off < 128; off <<= 1) {
        int add = (t >= off) ? sh[t - off] : 0;
        __syncthreads();
        sh[t] += add;
        __syncthreads();
    }
    if (t < NB) g_bsum[t] = sh[t] - v;
}

__global__ void scan3_kernel() {
    int i = blockIdx.x * blockDim.x + threadIdx.x;
    if (i < NN) {
        int o = g_tmp[i] + g_bsum[i >> 10];
        g_off[i] = o;
        g_cur[i] = o;
    }
    if (i == 0) g_off[NN] = EE;
}

// ---------------- fused: CSR scatter + edge logit + leaky + exp --------------
__global__ void scatter_edge_kernel(const int* __restrict__ es,
                                    const int* __restrict__ ed,
                                    const float* __restrict__ fe,
                                    const float* __restrict__ Wae) {
    int i = blockIdx.x * blockDim.x + threadIdx.x;
    if (i >= EE) return;

    int s = es[i], d = ed[i];
    int pos = atomicAdd(&g_cur[d], 1);
    g_psrc[pos] = s;

    float4 x0 = *(const float4*)(fe + (size_t)i * DE);
    float4 x1 = *(const float4*)(fe + (size_t)i * DE + 4);

    float ae0 = x0.x * __ldg(Wae + 0) + x0.y * __ldg(Wae + 1) +
                x0.z * __ldg(Wae + 2) + x0.w * __ldg(Wae + 3) +
                x1.x * __ldg(Wae + 4) + x1.y * __ldg(Wae + 5) +
                x1.z * __ldg(Wae + 6) + x1.w * __ldg(Wae + 7);
    float ae1 = x0.x * __ldg(Wae + 8)  + x0.y * __ldg(Wae + 9) +
                x0.z * __ldg(Wae + 10) + x0.w * __ldg(Wae + 11) +
                x1.x * __ldg(Wae + 12) + x1.y * __ldg(Wae + 13) +
                x1.z * __ldg(Wae + 14) + x1.w * __ldg(Wae + 15);

    float2 as = g_asrc[s];
    float2 ad = g_adst[d];
    float e0 = as.x + ad.x + ae0;
    float e1 = as.y + ad.y + ae1;
    e0 = (e0 >= 0.f) ? e0 : NEG_SLOPE * e0;
    e1 = (e1 >= 0.f) ? e1 : NEG_SLOPE * e1;
    g_ep[pos] = make_float2(__expf(e0), __expf(e1));
}

// ---------------- wmma GEMM: 3-stage A pipeline, B full-K resident -----------
#define LDA 40
#define LDC 132
#define A_BUF_BYTES (128 * LDA * 2)
#define B_OFF (3 * A_BUF_BYTES)
template <int K>
__global__ void __launch_bounds__(256)
gemm_h_kernel(const __half* __restrict__ A,
              const __half* __restrict__ B0, const __half* __restrict__ B1,
              const float* __restrict__ bias0, const float* __restrict__ bias1,
              const __half* __restrict__ add,
              float* __restrict__ Cf,
              __half* __restrict__ C0h, __half* __restrict__ C1h,
              int M, int mode) {
    extern __shared__ char dynsm[];
    __half* Asb[3] = {(__half*)dynsm, (__half*)(dynsm + A_BUF_BYTES),
                      (__half*)(dynsm + 2 * A_BUF_BYTES)};
    __half* Bs = (__half*)(dynsm + B_OFF);
    float*  Cs = (float*)(dynsm + B_OFF);
    const int LDB = K + 8;

    const __half* B    = (blockIdx.x == 0) ? B0 : B1;
    const float*  bias = (blockIdx.x == 0) ? bias0 : bias1;
    __half*       Ch   = (blockIdx.x == 0) ? C0h : C1h;

    int bm = blockIdx.y * 128;
    int t  = threadIdx.x;
    int w  = t >> 5;
    int wm = w & 3;
    int wn = w >> 2;

    int lr = t >> 1;
    int lh = (t & 1) * 16;
    int arow = bm + lr;
    bool ap_ok = (arow < M);
    const __half* a_base = A + (size_t)(ap_ok ? arow : (M - 1)) * K + lh;

    constexpr int nIter = K >> 5;

    {
        constexpr int cpr = K >> 3;
        for (int idx = t; idx < 128 * cpr; idx += 256) {
            int row = idx / cpr;
            int ch = (idx % cpr) * 8;
            cp16cg(&Bs[row * LDB + ch], B + (size_t)row * K + ch, true);
        }
        cp16cg(&Asb[0][lr * LDA + lh], a_base, ap_ok);
        cp16cg(&Asb[0][lr * LDA + lh + 8], a_base + 8, ap_ok);
        cp_commit();
        if (nIter > 1) {
            cp16cg(&Asb[1][lr * LDA + lh], a_base + 32, ap_ok);
            cp16cg(&Asb[1][lr * LDA + lh + 8], a_base + 40, ap_ok);
        }
        cp_commit();
    }

    wmma::fragment<wmma::accumulator, 16, 16, 16, float> cf[2][4];
#pragma unroll
    for (int i = 0; i < 2; i++)
#pragma unroll
        for (int j = 0; j < 4; j++) wmma::fill_fragment(cf[i][j], 0.0f);

#pragma unroll
    for (int it = 0; it < nIter; it++) {
        cp_wait<1>();
        __syncthreads();

        __half* As = Asb[it % 3];
        int kb = it << 5;
#pragma unroll
        for (int ks = 0; ks < 32; ks += 16) {
            wmma::fragment<wmma::matrix_a, 16, 16, 16, __half, wmma::row_major> af[2];
            wmma::fragment<wmma::matrix_b, 16, 16, 16, __half, wmma::col_major> bf[4];
#pragma unroll
            for (int i = 0; i < 2; i++)
                wmma::load_matrix_sync(af[i], &As[(wm * 32 + i * 16) * LDA + ks], LDA);
#pragma unroll
            for (int j = 0; j < 4; j++)
                wmma::load_matrix_sync(bf[j], &Bs[(wn * 64 + j * 16) * LDB + kb + ks], LDB);
#pragma unroll
            for (int i = 0; i < 2; i++)
#pragma unroll
                for (int j = 0; j < 4; j++)
                    wmma::mma_sync(cf[i][j], af[i], bf[j], cf[i][j]);
        }

        if (it + 2 < nIter) {
            int kt = (it + 2) << 5;
            __half* Ap = Asb[(it + 2) % 3];
            cp16cg(&Ap[lr * LDA + lh], a_base + kt, ap_ok);
            cp16cg(&Ap[lr * LDA + lh + 8], a_base + kt + 8, ap_ok);
        }
        cp_commit();
    }
    __syncthreads();

#pragma unroll
    for (int half = 0; half < 2; half++) {
        if ((wm >> 1) == half) {
            int wml = wm & 1;
#pragma unroll
            for (int i = 0; i < 2; i++)
#pragma unroll
                for (int j = 0; j < 4; j++)
                    wmma::store_matrix_sync(
                        &Cs[(wml * 32 + i * 16) * LDC + wn * 64 + j * 16],
                        cf[i][j], LDC, wmma::mem_row_major);
        }
        __syncthreads();

        {
            int r = t >> 2;
            int cb = (t & 3) * 32;
            int row = bm + half * 64 + r;
            if (row < M) {
#pragma unroll
                for (int j = 0; j < 32; j += 4) {
                    float4 v = *(float4*)&Cs[r * LDC + cb + j];
                    if (bias) {
                        float4 b = *(const float4*)(bias + cb + j);
                        v.x += b.x; v.y += b.y; v.z += b.z; v.w += b.w;
                    }
                    if (mode == 1) {
                        uint2 ru = *(const uint2*)(add + (size_t)row * HF + cb + j);
                        __half2* rh = (__half2*)&ru;
                        float2 r0 = __half22float2(rh[0]);
                        float2 r1 = __half22float2(rh[1]);
                        v.x = fmaxf(v.x, 0.f) + r0.x;
                        v.y = fmaxf(v.y, 0.f) + r0.y;
                        v.z = fmaxf(v.z, 0.f) + r1.x;
                        v.w = fmaxf(v.w, 0.f) + r1.y;
                        *(float4*)(Cf + (size_t)row * HF + cb + j) = v;
                    } else {
                        __half2 p[2] = {__floats2half2_rn(v.x, v.y),
                                        __floats2half2_rn(v.z, v.w)};
                        *(uint2*)(Ch + (size_t)row * HF + cb + j) = *(uint2*)p;
                    }
                }
            }
        }
        __syncthreads();
    }
}

// ---------------- pull aggregation: unroll-4, warp per dst node --------------
__global__ void agg_kernel() {
    int warp = (blockIdx.x * blockDim.x + threadIdx.x) >> 5;
    if (warp >= NN) return;
    int lane = threadIdx.x & 31;

    int row = g_off[warp];
    int end = g_off[warp + 1];

    const int elem = lane * 4;
    const bool h0 = (lane < 16);
    float z = 0.f;
    float a0 = 0.f, a1 = 0.f, a2 = 0.f, a3 = 0.f;

    int j = row;
    for (; j + 4 <= end; j += 4) {
        float2 e0 = g_ep[j],     e1 = g_ep[j + 1];
        float2 e2 = g_ep[j + 2], e3 = g_ep[j + 3];
        int s0 = g_psrc[j],     s1 = g_psrc[j + 1];
        int s2 = g_psrc[j + 2], s3 = g_psrc[j + 3];
        float c0 = h0 ? e0.x : e0.y;
        float c1 = h0 ? e1.x : e1.y;
        float c2 = h0 ? e2.x : e2.y;
        float c3 = h0 ? e3.x : e3.y;
        z += (c0 + c1) + (c2 + c3);
        uint2 q0 = *(const uint2*)(g_hsrc_h + (size_t)s0 * HF + elem);
        uint2 q1 = *(const uint2*)(g_hsrc_h + (size_t)s1 * HF + elem);
        uint2 q2 = *(const uint2*)(g_hsrc_h + (size_t)s2 * HF + elem);
        uint2 q3 = *(const uint2*)(g_hsrc_h + (size_t)s3 * HF + elem);
        __half2* h0p = (__half2*)&q0;
        __half2* h1p = (__half2*)&q1;
        __half2* h2p = (__half2*)&q2;
        __half2* h3p = (__half2*)&q3;
        float2 f00 = __half22float2(h0p[0]), f01 = __half22float2(h0p[1]);
        float2 f10 = __half22float2(h1p[0]), f11 = __half22float2(h1p[1]);
        float2 f20 = __half22float2(h2p[0]), f21 = __half22float2(h2p[1]);
        float2 f30 = __half22float2(h3p[0]), f31 = __half22float2(h3p[1]);
        a0 = fmaf(f00.x, c0, a0); a1 = fmaf(f00.y, c0, a1);
        a2 = fmaf(f01.x, c0, a2); a3 = fmaf(f01.y, c0, a3);
        a0 = fmaf(f10.x, c1, a0); a1 = fmaf(f10.y, c1, a1);
        a2 = fmaf(f11.x, c1, a2); a3 = fmaf(f11.y, c1, a3);
        a0 = fmaf(f20.x, c2, a0); a1 = fmaf(f20.y, c2, a1);
        a2 = fmaf(f21.x, c2, a2); a3 = fmaf(f21.y, c2, a3);
        a0 = fmaf(f30.x, c3, a0); a1 = fmaf(f30.y, c3, a1);
        a2 = fmaf(f31.x, c3, a2); a3 = fmaf(f31.y, c3, a3);
    }
    for (; j < end; j++) {
        float2 e0 = g_ep[j];
        int s0 = g_psrc[j];
        float c0 = h0 ? e0.x : e0.y;
        z += c0;
        uint2 q0 = *(const uint2*)(g_hsrc_h + (size_t)s0 * HF + elem);
        __half2* hp = (__half2*)&q0;
        float2 f0 = __half22float2(hp[0]), f1 = __half22float2(hp[1]);
        a0 = fmaf(f0.x, c0, a0); a1 = fmaf(f0.y, c0, a1);
        a2 = fmaf(f1.x, c0, a2); a3 = fmaf(f1.y, c0, a3);
    }

    float invz = (end > row) ? __fdividef(1.f, z) : 0.f;
    __half2 hh[2] = {__floats2half2_rn(a0 * invz, a1 * invz),
                     __floats2half2_rn(a2 * invz, a3 * invz)};
    *(uint2*)(g_rst_h + (size_t)warp * HF + elem) = *(uint2*)hh;
}

// ---------------- launch -----------------------------------------------------
extern "C" void kernel_launch(void* const* d_in, const int* in_sizes, int n_in,
                              void* d_out, int out_size) {
    const float* feat_src    = (const float*)d_in[0];
    const float* feat_edge   = (const float*)d_in[1];
    const int*   edge_src    = (const int*)d_in[2];
    const int*   edge_dst    = (const int*)d_in[3];
    const float* W_src       = (const float*)d_in[4];
    const float* W_dst       = (const float*)d_in[5];
    const float* b_dst       = (const float*)d_in[6];
    const float* W_attn_src  = (const float*)d_in[7];
    const float* W_attn_dst  = (const float*)d_in[8];
    const float* W_attn_edge = (const float*)d_in[9];
    const float* W_ngnn      = (const float*)d_in[10];
    const float* b_ngnn      = (const float*)d_in[11];
    float* out = (float*)d_out;

    __half* feat_h;  cudaGetSymbolAddress((void**)&feat_h,  g_feat_h);
    __half* wsrc_h;  cudaGetSymbolAddress((void**)&wsrc_h,  g_wsrc_h);
    __half* wdst_h;  cudaGetSymbolAddress((void**)&wdst_h,  g_wdst_h);
    __half* wngnn_h; cudaGetSymbolAddress((void**)&wngnn_h, g_wngnn_h);
    __half* hsrc_h;  cudaGetSymbolAddress((void**)&hsrc_h,  g_hsrc_h);
    __half* hdst_h;  cudaGetSymbolAddress((void**)&hdst_h,  g_hdst_h);
    __half* rst_h;   cudaGetSymbolAddress((void**)&rst_h,   g_rst_h);

    const int smem256 = B_OFF + 128 * (256 + 8) * 2;
    const int smem128 = B_OFF + 128 * (128 + 8) * 2;

    static bool attr_set = false;
    if (!attr_set) {
        cudaFuncSetAttribute(gemm_h_kernel<256>,
                             cudaFuncAttributeMaxDynamicSharedMemorySize, smem256);
        cudaFuncSetAttribute(gemm_h_kernel<128>,
                             cudaFuncAttributeMaxDynamicSharedMemorySize, smem128);
        attr_set = true;
    }

    // 0: weights + histogram + feat conversion + attention logits
    phase1_kernel<<<WCONV_BLOCKS + HIST_BLOCKS + 1024, 256>>>(
        feat_src, W_attn_src, W_attn_dst, W_src, W_dst, W_ngnn, edge_dst);

    // 1-2: CSR scan (scan1 self-cleans g_cnt)
    scan1_kernel<<<NB, 1024>>>();
    scan2_kernel<<<1, 128>>>();

    // 3: node GEMMs (h_src & h_dst fp16) — profiled slot
    gemm_h_kernel<256><<<dim3(2, (NN + 127) / 128), 256, smem256>>>(
        feat_h, wsrc_h, wdst_h, nullptr, b_dst, nullptr,
        nullptr, hsrc_h, hdst_h, NN, 0);

    // 4: finish CSR offsets
    scan3_kernel<<<(NN + 255) / 256, 256>>>();

    // 5: fused scatter + edge logits + exp
    scatter_edge_kernel<<<(EE + 255) / 256, 256>>>(edge_src, edge_dst,
                                                   feat_edge, W_attn_edge);

    // 6: pull aggregation (single-pass softmax + weighted sum, unroll-4)
    agg_kernel<<<(NN * 32 + 255) / 256, 256>>>();

    // 7: NGNN GEMM + ReLU + bias + fp16 residual -> fp32 out
    gemm_h_kernel<128><<<dim3(1, (NN + 127) / 128), 256, smem128>>>(
        rst_h, wngnn_h, wngnn_h, b_ngnn, b_ngnn, hdst_h,
        out, nullptr, nullptr, NN, 1);
}